// round 1
// baseline (speedup 1.0000x reference)
#include <cuda_runtime.h>
#include <math.h>

#define P_PIX 16384   // 128*128
#define NCH   384
#define NQKV  1152
#define HEADS 8
#define CH    48      // per-head channels
#define NWIN  64      // tokens per 8x8 window

// ---------------- scratch (device globals; no allocs allowed) ----------------
__device__ float g_qkv[2ll * NQKV * P_PIX];    // after 1x1 conv
__device__ float g_dw [2ll * NQKV * P_PIX];    // after depthwise: q|k|v
__device__ float g_sum[2ll * NCH  * P_PIX];    // cout + sout (pre-proj)
__device__ float g_cnq[2 * NCH];
__device__ float g_cnk[2 * NCH];
__device__ float g_cpart[16 * 16 * CH * CH];   // split-K partials for cattn
__device__ float g_ccoef[16 * CH * CH];        // combined softmax coefficients

// ---------------- 1x1 conv as GEMM: Y[b][m][p] = sum_k W[m][k] X[b][k][p] ----
__global__ __launch_bounds__(256) void gemm1x1(
    const float* __restrict__ W, const float* __restrict__ X,
    float* __restrict__ Y, int M, int K)
{
    const int b  = blockIdx.z;
    const int m0 = blockIdx.y * 64;
    const int p0 = blockIdx.x * 128;
    const float* Xb = X + (size_t)b * K * P_PIX;
    float*       Yb = Y + (size_t)b * M * P_PIX;

    __shared__ float sA[8][64];
    __shared__ float sB[8][128];

    const int tid = threadIdx.x;
    const int tx = tid & 15;        // p-group
    const int ty = tid >> 4;        // m-group

    float acc[4][8];
#pragma unroll
    for (int i = 0; i < 4; i++)
#pragma unroll
        for (int j = 0; j < 8; j++) acc[i][j] = 0.f;

    for (int k0 = 0; k0 < K; k0 += 8) {
        // A tile: W[m0+m][k0+k] -> sA[k][m]
        {
            int e = tid;
#pragma unroll
            for (int r = 0; r < 2; r++, e += 256) {
                int m = e >> 3, k = e & 7;
                sA[k][m] = W[(size_t)(m0 + m) * K + (k0 + k)];
            }
        }
        // B tile: X[k0+k][p0+p] -> sB[k][p]  (float4)
        {
            int k = tid >> 5, p = (tid & 31) << 2;
            float4 v = *reinterpret_cast<const float4*>(&Xb[(size_t)(k0 + k) * P_PIX + p0 + p]);
            *reinterpret_cast<float4*>(&sB[k][p]) = v;
        }
        __syncthreads();
#pragma unroll
        for (int k = 0; k < 8; k++) {
            float a[4], bb[8];
#pragma unroll
            for (int i = 0; i < 4; i++) a[i] = sA[k][ty * 4 + i];
#pragma unroll
            for (int j = 0; j < 8; j++) bb[j] = sB[k][tx * 8 + j];
#pragma unroll
            for (int i = 0; i < 4; i++)
#pragma unroll
                for (int j = 0; j < 8; j++)
                    acc[i][j] = fmaf(a[i], bb[j], acc[i][j]);
        }
        __syncthreads();
    }
#pragma unroll
    for (int i = 0; i < 4; i++) {
        int m = m0 + ty * 4 + i;
#pragma unroll
        for (int j = 0; j < 8; j += 4) {
            float4 v = make_float4(acc[i][j], acc[i][j+1], acc[i][j+2], acc[i][j+3]);
            *reinterpret_cast<float4*>(&Yb[(size_t)m * P_PIX + p0 + tx * 8 + j]) = v;
        }
    }
}

// ---------------- depthwise 3x3, pad 1 ----------------
__global__ __launch_bounds__(256) void dwconv_kernel(
    const float* __restrict__ in, const float* __restrict__ Wd, float* __restrict__ out)
{
    long long idx = (long long)blockIdx.x * 256 + threadIdx.x;  // 2*1152*16384
    int p  = (int)(idx & 16383);
    int bc = (int)(idx >> 14);
    int ch = bc % NQKV;
    int x = p & 127, y = p >> 7;
    const float* ip = in + (size_t)bc * P_PIX;
    const float* w  = Wd + ch * 9;
    float s = 0.f;
#pragma unroll
    for (int dy = -1; dy <= 1; dy++) {
        int yy = y + dy;
        if ((unsigned)yy >= 128u) continue;
#pragma unroll
        for (int dx = -1; dx <= 1; dx++) {
            int xx = x + dx;
            if ((unsigned)xx >= 128u) continue;
            s = fmaf(w[(dy + 1) * 3 + (dx + 1)], ip[yy * 128 + xx], s);
        }
    }
    out[idx] = s;
}

// ---------------- per-channel-row L2 norms over 16384 (q and k) -------------
__global__ __launch_bounds__(256) void chan_norms_kernel(
    const float* __restrict__ dw, float* __restrict__ nq, float* __restrict__ nk)
{
    int row = blockIdx.x;            // 0..1535
    int b = row / 768;
    int r = row % 768;               // 0..383 q, 384..767 k
    const float* p = dw + ((size_t)b * NQKV + r) * P_PIX;
    float s = 0.f;
    for (int i = threadIdx.x; i < P_PIX; i += 256) { float v = p[i]; s = fmaf(v, v, s); }
    __shared__ float red[256];
    red[threadIdx.x] = s; __syncthreads();
    for (int st = 128; st > 0; st >>= 1) {
        if (threadIdx.x < st) red[threadIdx.x] += red[threadIdx.x + st];
        __syncthreads();
    }
    if (threadIdx.x == 0) {
        float n = fmaxf(sqrtf(red[0]), 1e-12f);
        if (r < NCH) nq[b * NCH + r] = n; else nk[b * NCH + (r - NCH)] = n;
    }
}

// ---------------- cattn raw dots, split-K partials (deterministic) ----------
__global__ __launch_bounds__(256) void cattn_kernel(
    const float* __restrict__ dw, float* __restrict__ part)
{
    int bh = blockIdx.y;             // b*8+h (0..15)
    int b = bh >> 3, h = bh & 7;
    int kbase = blockIdx.x * 1024;   // split 0..15
    const float* qb = dw + ((size_t)b * NQKV + h * CH) * P_PIX;
    const float* kb = dw + ((size_t)b * NQKV + NCH + h * CH) * P_PIX;

    __shared__ float sq[CH][65];
    __shared__ float sk[CH][65];

    float acc[9];
#pragma unroll
    for (int i = 0; i < 9; i++) acc[i] = 0.f;

    for (int kc = 0; kc < 1024; kc += 64) {
        int kpos = kbase + kc;
        for (int e = threadIdx.x; e < CH * 64; e += 256) {
            int r = e >> 6, c = e & 63;
            sq[r][c] = qb[(size_t)r * P_PIX + kpos + c];
            sk[r][c] = kb[(size_t)r * P_PIX + kpos + c];
        }
        __syncthreads();
#pragma unroll
        for (int o = 0; o < 9; o++) {
            int e = threadIdx.x + o * 256;
            int i = e / CH, j = e % CH;
            float s = 0.f;
#pragma unroll 8
            for (int kk = 0; kk < 64; kk++) s = fmaf(sq[i][kk], sk[j][kk], s);
            acc[o] += s;
        }
        __syncthreads();
    }
#pragma unroll
    for (int o = 0; o < 9; o++) {
        int e = threadIdx.x + o * 256;
        int i = e / CH, j = e % CH;
        part[((size_t)blockIdx.x * 16 + bh) * (CH * CH) + i * CH + j] = acc[o];
    }
}

// ------- channel branch: combined top-k softmax coefficients (one warp/row) --
__global__ __launch_bounds__(256) void chan_coef_kernel(
    const float* __restrict__ part, const float* __restrict__ nq,
    const float* __restrict__ nk, const float* __restrict__ temp,
    const float* __restrict__ w1p, const float* __restrict__ w2p,
    const float* __restrict__ w3p, const float* __restrict__ w4p,
    float* __restrict__ coef)
{
    const int warp = threadIdx.x >> 5, ln = threadIdx.x & 31;
    const int row = blockIdx.x * 8 + warp;     // (b*8+h)*48 + i, 0..767
    const int bh = row / CH, i = row % CH;
    const int b = bh >> 3, h = bh & 7;
    const float t = temp[h];
    const float inq = 1.f / nq[b * NCH + h * CH + i];
    const int KT[4] = {23, 31, 35, 37};        // rank targets (k-1) for k=24,32,36,38
    float wts[4] = {w1p[0], w2p[0], w3p[0], w4p[0]};

    __shared__ float sa[8][CH];
    __shared__ float sth[8][4];

    int j0 = ln, j1 = ln + 32;
    // deterministic split-K reduction
    float d0 = 0.f, d1 = 0.f;
    for (int s = 0; s < 16; s++) {
        const float* pr = part + ((size_t)s * 16 + bh) * (CH * CH) + i * CH;
        d0 += pr[j0];
        if (j1 < CH) d1 += pr[j1];
    }
    float a0 = d0 * inq / nk[b * NCH + h * CH + j0] * t;
    float a1 = (j1 < CH) ? d1 * inq / nk[b * NCH + h * CH + j1] * t : -INFINITY;
    sa[warp][j0] = a0;
    if (j1 < CH) sa[warp][j1] = a1;
    __syncwarp();

    int r0 = 0, r1 = 0;
    for (int q = 0; q < CH; q++) {
        float aq = sa[warp][q];
        r0 += (aq > a0) || (aq == a0 && q < j0);
        if (j1 < CH) r1 += (aq > a1) || (aq == a1 && q < j1);
    }
#pragma unroll
    for (int kx = 0; kx < 4; kx++) {
        if (r0 == KT[kx]) sth[warp][kx] = a0;
        if (j1 < CH && r1 == KT[kx]) sth[warp][kx] = a1;
    }
    __syncwarp();

    float m = fmaxf(a0, a1);
#pragma unroll
    for (int o = 16; o; o >>= 1) m = fmaxf(m, __shfl_xor_sync(0xffffffffu, m, o));
    float e0 = expf(a0 - m);
    float e1 = (j1 < CH) ? expf(a1 - m) : 0.f;

    float c0 = 0.f, c1 = 0.f;
#pragma unroll
    for (int kx = 0; kx < 4; kx++) {
        float th = sth[warp][kx];
        float zz = (a0 >= th ? e0 : 0.f) + ((j1 < CH && a1 >= th) ? e1 : 0.f);
#pragma unroll
        for (int o = 16; o; o >>= 1) zz += __shfl_xor_sync(0xffffffffu, zz, o);
        float f = wts[kx] / zz;
        if (a0 >= th) c0 += f;
        if (j1 < CH && a1 >= th) c1 += f;
    }
    coef[row * CH + j0] = e0 * c0;
    if (j1 < CH) coef[row * CH + j1] = e1 * c1;
}

// ---------------- cout = coef @ vc, writes g_sum ----------------
__global__ __launch_bounds__(256) void cout_kernel(
    const float* __restrict__ coef, const float* __restrict__ dw,
    float* __restrict__ out)
{
    int bh = blockIdx.y; int b = bh >> 3, h = bh & 7;
    int p = blockIdx.x * 256 + threadIdx.x;
    __shared__ float sc[CH * CH];
    for (int e = threadIdx.x; e < CH * CH; e += 256) sc[e] = coef[bh * CH * CH + e];
    __syncthreads();
    const float* vb = dw + ((size_t)b * NQKV + 2 * NCH + h * CH) * P_PIX + p;
    float acc[CH];
#pragma unroll
    for (int i = 0; i < CH; i++) acc[i] = 0.f;
    for (int j = 0; j < CH; j++) {
        float vj = vb[(size_t)j * P_PIX];
#pragma unroll
        for (int i = 0; i < CH; i++) acc[i] = fmaf(sc[i * CH + j], vj, acc[i]);
    }
    float* ob = out + ((size_t)b * NCH + h * CH) * P_PIX + p;
#pragma unroll
    for (int i = 0; i < CH; i++) ob[(size_t)i * P_PIX] = acc[i];
}

// ---------------- fused spatial window attention ----------------
__global__ __launch_bounds__(256) void spatial_kernel(
    const float* __restrict__ dw, const float* __restrict__ temp,
    const float* __restrict__ w1p, const float* __restrict__ w2p,
    const float* __restrict__ w3p, const float* __restrict__ w4p,
    float* __restrict__ out)
{
    extern __shared__ float smem[];
    float* sq  = smem;                 // 64*49
    float* sk2 = sq  + 64 * 49;        // 64*49
    float* sv  = sk2 + 64 * 49;        // 64*48
    float* sat = sv  + 64 * 48;        // 64*65
    float* nq  = sat + 64 * 65;        // 64
    float* nk  = nq  + 64;             // 64
    float* sth = nk  + 64;             // 64*4

    const int win = blockIdx.x;                  // 0..511
    const int head = blockIdx.y;                 // 0..7
    const int b = win >> 8, wy = (win >> 4) & 15, wx = win & 15;
    const int tid = threadIdx.x;

    const size_t base = ((size_t)b * NQKV + head * CH) * P_PIX + (size_t)(wy * 8) * 128 + wx * 8;

    for (int e = tid; e < NWIN * CH; e += 256) {
        int c = e >> 6, n = e & 63;
        int iy = n >> 3, ix = n & 7;
        size_t off = (size_t)c * P_PIX + iy * 128 + ix;
        sq [n * 49 + c] = dw[base + off];
        sk2[n * 49 + c] = dw[base + (size_t)NCH * P_PIX + off];
        sv [n * 48 + c] = dw[base + (size_t)(2 * NCH) * P_PIX + off];
    }
    __syncthreads();

    if (tid < 128) {
        int n = tid & 63;
        const float* src = (tid < 64) ? sq : sk2;
        float s = 0.f;
#pragma unroll
        for (int c = 0; c < CH; c++) { float v = src[n * 49 + c]; s = fmaf(v, v, s); }
        float nn = fmaxf(sqrtf(s), 1e-12f);
        if (tid < 64) nq[n] = nn; else nk[n] = nn;
    }
    __syncthreads();

    // temperature broadcast index after the reference's dim-remix: wx & 7
    const float t = temp[wx & 7];
#pragma unroll
    for (int o = 0; o < 16; o++) {
        int e = tid + o * 256;
        int n = e >> 6, m = e & 63;
        float s = 0.f;
#pragma unroll 8
        for (int c = 0; c < CH; c++) s = fmaf(sq[n * 49 + c], sk2[m * 49 + c], s);
        sat[n * 65 + m] = s / (nq[n] * nk[m]) * t;
    }
    __syncthreads();

    const int warp = tid >> 5, ln = tid & 31;
    const int KT[4] = {31, 41, 47, 50};   // rank targets for k=32,42,48,51
    float wts[4] = {w1p[0], w2p[0], w3p[0], w4p[0]};

    for (int rr = 0; rr < 8; rr++) {
        int n = warp * 8 + rr;
        float a0 = sat[n * 65 + ln];
        float a1 = sat[n * 65 + ln + 32];
        int r0 = 0, r1 = 0;
        for (int i2 = 0; i2 < NWIN; i2++) {
            float ai = sat[n * 65 + i2];
            r0 += (ai > a0) || (ai == a0 && i2 < ln);
            r1 += (ai > a1) || (ai == a1 && i2 < ln + 32);
        }
#pragma unroll
        for (int kx = 0; kx < 4; kx++) {
            if (r0 == KT[kx]) sth[n * 4 + kx] = a0;
            if (r1 == KT[kx]) sth[n * 4 + kx] = a1;
        }
        __syncwarp();

        float m = fmaxf(a0, a1);
#pragma unroll
        for (int o = 16; o; o >>= 1) m = fmaxf(m, __shfl_xor_sync(0xffffffffu, m, o));
        float e0 = expf(a0 - m), e1 = expf(a1 - m);

        float c0 = 0.f, c1 = 0.f;
#pragma unroll
        for (int kx = 0; kx < 4; kx++) {
            float th = sth[n * 4 + kx];
            float zz = (a0 >= th ? e0 : 0.f) + (a1 >= th ? e1 : 0.f);
#pragma unroll
            for (int o = 16; o; o >>= 1) zz += __shfl_xor_sync(0xffffffffu, zz, o);
            float f = wts[kx] / zz;
            if (a0 >= th) c0 += f;
            if (a1 >= th) c1 += f;
        }
        __syncwarp();
        sat[n * 65 + ln]      = e0 * c0;
        sat[n * 65 + ln + 32] = e1 * c1;
        __syncwarp();
    }
    __syncthreads();

    // out token n lands at contiguous p = wy*1024 + wx*64 + n (reference's reshape remix)
#pragma unroll
    for (int o = 0; o < 12; o++) {
        int e = tid + o * 256;
        int c = e >> 6, n = e & 63;
        float s = 0.f;
#pragma unroll 8
        for (int m = 0; m < NWIN; m++) s = fmaf(sat[n * 65 + m], sv[m * 48 + c], s);
        int p = wy * 1024 + wx * 64 + n;
        size_t oidx = ((size_t)b * NCH + head * CH + c) * P_PIX + p;
        out[oidx] += s;
    }
}

// ---------------- host launcher ----------------
extern "C" void kernel_launch(void* const* d_in, const int* in_sizes, int n_in,
                              void* d_out, int out_size)
{
    const float* x      = (const float*)d_in[0];
    const float* w_qkv  = (const float*)d_in[1];
    const float* w_dw   = (const float*)d_in[2];
    const float* w_proj = (const float*)d_in[3];
    const float* temp   = (const float*)d_in[4];
    const float* a1     = (const float*)d_in[5];
    const float* a2     = (const float*)d_in[6];
    const float* a3     = (const float*)d_in[7];
    const float* a4     = (const float*)d_in[8];
    float* out = (float*)d_out;

    float *qkv, *dwb, *sum, *cnq, *cnk, *cpart, *ccoef;
    cudaGetSymbolAddress((void**)&qkv,   g_qkv);
    cudaGetSymbolAddress((void**)&dwb,   g_dw);
    cudaGetSymbolAddress((void**)&sum,   g_sum);
    cudaGetSymbolAddress((void**)&cnq,   g_cnq);
    cudaGetSymbolAddress((void**)&cnk,   g_cnk);
    cudaGetSymbolAddress((void**)&cpart, g_cpart);
    cudaGetSymbolAddress((void**)&ccoef, g_ccoef);

    const int spatial_smem = (64*49*2 + 64*48 + 64*65 + 64 + 64 + 64*4) * 4;
    cudaFuncSetAttribute(spatial_kernel, cudaFuncAttributeMaxDynamicSharedMemorySize, 65536);

    // 1) qkv = 1x1 conv
    gemm1x1<<<dim3(P_PIX / 128, NQKV / 64, 2), 256>>>(w_qkv, x, qkv, NQKV, NCH);
    // 2) depthwise 3x3
    dwconv_kernel<<<(2 * NQKV * P_PIX) / 256, 256>>>(qkv, w_dw, dwb);
    // 3) channel-row norms (q, k)
    chan_norms_kernel<<<2 * 2 * NCH, 256>>>(dwb, cnq, cnk);
    // 4) cattn raw dots, split-K partials
    cattn_kernel<<<dim3(16, 16), 256>>>(dwb, cpart);
    // 5) combined channel softmax coefficients
    chan_coef_kernel<<<96, 256>>>(cpart, cnq, cnk, temp, a1, a2, a3, a4, ccoef);
    // 6) cout = coef @ v  (writes g_sum)
    cout_kernel<<<dim3(P_PIX / 256, 16), 256>>>(ccoef, dwb, sum);
    // 7) fused spatial window attention (adds into g_sum)
    spatial_kernel<<<dim3(512, HEADS), 256, spatial_smem>>>(dwb, temp, a1, a2, a3, a4, sum);
    // 8) proj 1x1 conv -> d_out
    gemm1x1<<<dim3(P_PIX / 128, NCH / 64, 2), 256>>>(w_proj, sum, out, NCH, NCH);
}

// round 2
// speedup vs baseline: 1.3875x; 1.3875x over previous
#include <cuda_runtime.h>
#include <math.h>

#define P_PIX 16384   // 128*128
#define NCH   384
#define NQKV  1152
#define HEADS 8
#define CH    48      // per-head channels
#define NWIN  64      // tokens per 8x8 window
#define CSPLIT 32     // cattn K splits

// ---------------- scratch (device globals; no allocs allowed) ----------------
__device__ float g_qkv[2ll * NQKV * P_PIX];    // after 1x1 conv
__device__ float g_dw [2ll * NQKV * P_PIX];    // after depthwise: q|k|v
__device__ float g_sum[2ll * NCH  * P_PIX];    // cout + sout (pre-proj)
__device__ float g_cnq[2 * NCH];
__device__ float g_cnk[2 * NCH];
__device__ float g_cpart[CSPLIT * 16 * CH * CH];   // split-K partials for cattn
__device__ float g_ccoef[16 * CH * CH];            // combined softmax coefficients

// ------- 1x1 conv as SGEMM: Y[b][m][p] = sum_k W[m][k] X[b][k][p] -----------
// 128x128 tile, BK=8, double-buffered, 8x8 micro-tile per thread.
__global__ __launch_bounds__(256) void gemm1x1(
    const float* __restrict__ W, const float* __restrict__ X,
    float* __restrict__ Y, int M, int K)
{
    const int b  = blockIdx.z;
    const int m0 = blockIdx.y * 128;
    const int p0 = blockIdx.x * 128;
    const float* Xb = X + (size_t)b * K * P_PIX;
    float*       Yb = Y + (size_t)b * M * P_PIX;

    __shared__ float sA[2][8][128];
    __shared__ float sB[2][8][128];

    const int tid = threadIdx.x;
    const int tr = tid >> 4;        // 0..15  (m-group)
    const int tc = tid & 15;        // 0..15  (p-group)

    // loader mapping
    const int aRow = tid >> 1;          // 0..127
    const int aK4  = (tid & 1) * 4;     // 0 or 4
    const int bK   = tid >> 5;          // 0..7
    const int bP4  = (tid & 31) * 4;    // 0..124

    const float* Aptr = &W[(size_t)(m0 + aRow) * K + aK4];
    const float* Bptr = &Xb[(size_t)bK * P_PIX + p0 + bP4];

    float acc[8][8];
#pragma unroll
    for (int i = 0; i < 8; i++)
#pragma unroll
        for (int j = 0; j < 8; j++) acc[i][j] = 0.f;

    // prologue: tile 0 -> buffer 0
    {
        float4 ra = *reinterpret_cast<const float4*>(Aptr);
        float4 rb = *reinterpret_cast<const float4*>(Bptr);
        sA[0][aK4 + 0][aRow] = ra.x;
        sA[0][aK4 + 1][aRow] = ra.y;
        sA[0][aK4 + 2][aRow] = ra.z;
        sA[0][aK4 + 3][aRow] = ra.w;
        *reinterpret_cast<float4*>(&sB[0][bK][bP4]) = rb;
    }
    __syncthreads();

    const int kIter = K >> 3;
    for (int t = 0; t < kIter; t++) {
        const int cb = t & 1;
        float4 ra, rb;
        if (t + 1 < kIter) {
            const int k0 = (t + 1) << 3;
            ra = *reinterpret_cast<const float4*>(Aptr + k0);
            rb = *reinterpret_cast<const float4*>(Bptr + (size_t)k0 * P_PIX);
        }
#pragma unroll
        for (int k = 0; k < 8; k++) {
            float4 a0 = *reinterpret_cast<const float4*>(&sA[cb][k][tr * 8]);
            float4 a1 = *reinterpret_cast<const float4*>(&sA[cb][k][tr * 8 + 4]);
            float4 b0 = *reinterpret_cast<const float4*>(&sB[cb][k][tc * 8]);
            float4 b1 = *reinterpret_cast<const float4*>(&sB[cb][k][tc * 8 + 4]);
            float av[8] = {a0.x, a0.y, a0.z, a0.w, a1.x, a1.y, a1.z, a1.w};
            float bv[8] = {b0.x, b0.y, b0.z, b0.w, b1.x, b1.y, b1.z, b1.w};
#pragma unroll
            for (int i = 0; i < 8; i++)
#pragma unroll
                for (int j = 0; j < 8; j++)
                    acc[i][j] = fmaf(av[i], bv[j], acc[i][j]);
        }
        if (t + 1 < kIter) {
            const int nb = cb ^ 1;
            sA[nb][aK4 + 0][aRow] = ra.x;
            sA[nb][aK4 + 1][aRow] = ra.y;
            sA[nb][aK4 + 2][aRow] = ra.z;
            sA[nb][aK4 + 3][aRow] = ra.w;
            *reinterpret_cast<float4*>(&sB[nb][bK][bP4]) = rb;
            __syncthreads();
        }
    }

#pragma unroll
    for (int i = 0; i < 8; i++) {
        const int m = m0 + tr * 8 + i;
        float* yp = &Yb[(size_t)m * P_PIX + p0 + tc * 8];
        *reinterpret_cast<float4*>(yp)     = make_float4(acc[i][0], acc[i][1], acc[i][2], acc[i][3]);
        *reinterpret_cast<float4*>(yp + 4) = make_float4(acc[i][4], acc[i][5], acc[i][6], acc[i][7]);
    }
}

// ---------------- depthwise 3x3, pad 1 ----------------
__global__ __launch_bounds__(256) void dwconv_kernel(
    const float* __restrict__ in, const float* __restrict__ Wd, float* __restrict__ out)
{
    long long idx = (long long)blockIdx.x * 256 + threadIdx.x;  // 2*1152*16384
    int p  = (int)(idx & 16383);
    int bc = (int)(idx >> 14);
    int ch = bc % NQKV;
    int x = p & 127, y = p >> 7;
    const float* ip = in + (size_t)bc * P_PIX;
    const float* w  = Wd + ch * 9;
    float s = 0.f;
#pragma unroll
    for (int dy = -1; dy <= 1; dy++) {
        int yy = y + dy;
        if ((unsigned)yy >= 128u) continue;
#pragma unroll
        for (int dx = -1; dx <= 1; dx++) {
            int xx = x + dx;
            if ((unsigned)xx >= 128u) continue;
            s = fmaf(w[(dy + 1) * 3 + (dx + 1)], ip[yy * 128 + xx], s);
        }
    }
    out[idx] = s;
}

// ---------------- per-channel-row L2 norms over 16384 (q and k) -------------
__global__ __launch_bounds__(256) void chan_norms_kernel(
    const float* __restrict__ dw, float* __restrict__ nq, float* __restrict__ nk)
{
    int row = blockIdx.x;            // 0..1535
    int b = row / 768;
    int r = row % 768;               // 0..383 q, 384..767 k
    const float* p = dw + ((size_t)b * NQKV + r) * P_PIX;
    float s = 0.f;
    for (int i = threadIdx.x * 4; i < P_PIX; i += 1024) {
        float4 v = *reinterpret_cast<const float4*>(&p[i]);
        s = fmaf(v.x, v.x, s); s = fmaf(v.y, v.y, s);
        s = fmaf(v.z, v.z, s); s = fmaf(v.w, v.w, s);
    }
    __shared__ float red[256];
    red[threadIdx.x] = s; __syncthreads();
    for (int st = 128; st > 0; st >>= 1) {
        if (threadIdx.x < st) red[threadIdx.x] += red[threadIdx.x + st];
        __syncthreads();
    }
    if (threadIdx.x == 0) {
        float n = fmaxf(sqrtf(red[0]), 1e-12f);
        if (r < NCH) nq[b * NCH + r] = n; else nk[b * NCH + (r - NCH)] = n;
    }
}

// ------ cattn raw dots, split-K partials, 3x3 register tiling ---------------
__global__ __launch_bounds__(256) void cattn_kernel(
    const float* __restrict__ dw, float* __restrict__ part)
{
    const int bh = blockIdx.y;             // b*8+h (0..15)
    const int b = bh >> 3, h = bh & 7;
    const int kbase = blockIdx.x * (P_PIX / CSPLIT);   // 512 positions per split
    const float* qb = dw + ((size_t)b * NQKV + h * CH) * P_PIX;
    const float* kb = dw + ((size_t)b * NQKV + NCH + h * CH) * P_PIX;

    __shared__ float sq[CH][65];
    __shared__ float sk[CH][65];

    const int tid = threadIdx.x;
    const int ti = tid >> 4, tj = tid & 15;
    const int i0 = ti * 3, j0 = tj * 3;

    float acc[3][3];
#pragma unroll
    for (int r = 0; r < 3; r++)
#pragma unroll
        for (int c = 0; c < 3; c++) acc[r][c] = 0.f;

    for (int kc = 0; kc < P_PIX / CSPLIT; kc += 64) {
        const int kpos = kbase + kc;
        for (int e = tid; e < CH * 16; e += 256) {     // float4 loads
            int r = e >> 4, c4 = (e & 15) * 4;
            float4 vq = *reinterpret_cast<const float4*>(&qb[(size_t)r * P_PIX + kpos + c4]);
            float4 vk = *reinterpret_cast<const float4*>(&kb[(size_t)r * P_PIX + kpos + c4]);
            sq[r][c4] = vq.x; sq[r][c4+1] = vq.y; sq[r][c4+2] = vq.z; sq[r][c4+3] = vq.w;
            sk[r][c4] = vk.x; sk[r][c4+1] = vk.y; sk[r][c4+2] = vk.z; sk[r][c4+3] = vk.w;
        }
        __syncthreads();
#pragma unroll 8
        for (int kk = 0; kk < 64; kk++) {
            float a0 = sq[i0][kk], a1 = sq[i0+1][kk], a2 = sq[i0+2][kk];
            float b0 = sk[j0][kk], b1 = sk[j0+1][kk], b2 = sk[j0+2][kk];
            acc[0][0] = fmaf(a0, b0, acc[0][0]);
            acc[0][1] = fmaf(a0, b1, acc[0][1]);
            acc[0][2] = fmaf(a0, b2, acc[0][2]);
            acc[1][0] = fmaf(a1, b0, acc[1][0]);
            acc[1][1] = fmaf(a1, b1, acc[1][1]);
            acc[1][2] = fmaf(a1, b2, acc[1][2]);
            acc[2][0] = fmaf(a2, b0, acc[2][0]);
            acc[2][1] = fmaf(a2, b1, acc[2][1]);
            acc[2][2] = fmaf(a2, b2, acc[2][2]);
        }
        __syncthreads();
    }
    float* pr = &part[((size_t)blockIdx.x * 16 + bh) * (CH * CH)];
#pragma unroll
    for (int r = 0; r < 3; r++)
#pragma unroll
        for (int c = 0; c < 3; c++)
            pr[(i0 + r) * CH + (j0 + c)] = acc[r][c];
}

// ------- channel branch: combined top-k softmax coefficients (one warp/row) --
__global__ __launch_bounds__(256) void chan_coef_kernel(
    const float* __restrict__ part, const float* __restrict__ nq,
    const float* __restrict__ nk, const float* __restrict__ temp,
    const float* __restrict__ w1p, const float* __restrict__ w2p,
    const float* __restrict__ w3p, const float* __restrict__ w4p,
    float* __restrict__ coef)
{
    const int warp = threadIdx.x >> 5, ln = threadIdx.x & 31;
    const int row = blockIdx.x * 8 + warp;     // (b*8+h)*48 + i, 0..767
    const int bh = row / CH, i = row % CH;
    const int b = bh >> 3, h = bh & 7;
    const float t = temp[h];
    const float inq = 1.f / nq[b * NCH + h * CH + i];
    const int KT[4] = {23, 31, 35, 37};        // rank targets (k-1) for k=24,32,36,38
    float wts[4] = {w1p[0], w2p[0], w3p[0], w4p[0]};

    __shared__ float sa[8][CH];
    __shared__ float sth[8][4];

    int j0 = ln, j1 = ln + 32;
    // deterministic split-K reduction
    float d0 = 0.f, d1 = 0.f;
    for (int s = 0; s < CSPLIT; s++) {
        const float* pr = part + ((size_t)s * 16 + bh) * (CH * CH) + i * CH;
        d0 += pr[j0];
        if (j1 < CH) d1 += pr[j1];
    }
    float a0 = d0 * inq / nk[b * NCH + h * CH + j0] * t;
    float a1 = (j1 < CH) ? d1 * inq / nk[b * NCH + h * CH + j1] * t : -INFINITY;
    sa[warp][j0] = a0;
    if (j1 < CH) sa[warp][j1] = a1;
    __syncwarp();

    int r0 = 0, r1 = 0;
    for (int q = 0; q < CH; q++) {
        float aq = sa[warp][q];
        r0 += (aq > a0) || (aq == a0 && q < j0);
        if (j1 < CH) r1 += (aq > a1) || (aq == a1 && q < j1);
    }
#pragma unroll
    for (int kx = 0; kx < 4; kx++) {
        if (r0 == KT[kx]) sth[warp][kx] = a0;
        if (j1 < CH && r1 == KT[kx]) sth[warp][kx] = a1;
    }
    __syncwarp();

    float m = fmaxf(a0, a1);
#pragma unroll
    for (int o = 16; o; o >>= 1) m = fmaxf(m, __shfl_xor_sync(0xffffffffu, m, o));
    float e0 = expf(a0 - m);
    float e1 = (j1 < CH) ? expf(a1 - m) : 0.f;

    float c0 = 0.f, c1 = 0.f;
#pragma unroll
    for (int kx = 0; kx < 4; kx++) {
        float th = sth[warp][kx];
        float zz = (a0 >= th ? e0 : 0.f) + ((j1 < CH && a1 >= th) ? e1 : 0.f);
#pragma unroll
        for (int o = 16; o; o >>= 1) zz += __shfl_xor_sync(0xffffffffu, zz, o);
        float f = wts[kx] / zz;
        if (a0 >= th) c0 += f;
        if (j1 < CH && a1 >= th) c1 += f;
    }
    coef[row * CH + j0] = e0 * c0;
    if (j1 < CH) coef[row * CH + j1] = e1 * c1;
}

// ---------------- cout = coef @ vc, writes g_sum ----------------
__global__ __launch_bounds__(256) void cout_kernel(
    const float* __restrict__ coef, const float* __restrict__ dw,
    float* __restrict__ out)
{
    int bh = blockIdx.y; int b = bh >> 3, h = bh & 7;
    int p = blockIdx.x * 256 + threadIdx.x;
    __shared__ float sc[CH * CH];
    for (int e = threadIdx.x; e < CH * CH; e += 256) sc[e] = coef[bh * CH * CH + e];
    __syncthreads();
    const float* vb = dw + ((size_t)b * NQKV + 2 * NCH + h * CH) * P_PIX + p;
    float acc[CH];
#pragma unroll
    for (int i = 0; i < CH; i++) acc[i] = 0.f;
    for (int j = 0; j < CH; j++) {
        float vj = vb[(size_t)j * P_PIX];
#pragma unroll
        for (int i = 0; i < CH; i++) acc[i] = fmaf(sc[i * CH + j], vj, acc[i]);
    }
    float* ob = out + ((size_t)b * NCH + h * CH) * P_PIX + p;
#pragma unroll
    for (int i = 0; i < CH; i++) ob[(size_t)i * P_PIX] = acc[i];
}

// ---------------- fused spatial window attention ----------------
__global__ __launch_bounds__(256) void spatial_kernel(
    const float* __restrict__ dw, const float* __restrict__ temp,
    const float* __restrict__ w1p, const float* __restrict__ w2p,
    const float* __restrict__ w3p, const float* __restrict__ w4p,
    float* __restrict__ out)
{
    extern __shared__ float smem[];
    float* sq  = smem;                 // 64*49
    float* sk2 = sq  + 64 * 49;        // 64*49
    float* sv  = sk2 + 64 * 49;        // 64*48
    float* sat = sv  + 64 * 48;        // 64*65
    float* nq  = sat + 64 * 65;        // 64
    float* nk  = nq  + 64;             // 64
    float* sth = nk  + 64;             // 64*4

    const int win = blockIdx.x;                  // 0..511
    const int head = blockIdx.y;                 // 0..7
    const int b = win >> 8, wy = (win >> 4) & 15, wx = win & 15;
    const int tid = threadIdx.x;

    const size_t base = ((size_t)b * NQKV + head * CH) * P_PIX + (size_t)(wy * 8) * 128 + wx * 8;

    for (int e = tid; e < NWIN * CH; e += 256) {
        int c = e >> 6, n = e & 63;
        int iy = n >> 3, ix = n & 7;
        size_t off = (size_t)c * P_PIX + iy * 128 + ix;
        sq [n * 49 + c] = dw[base + off];
        sk2[n * 49 + c] = dw[base + (size_t)NCH * P_PIX + off];
        sv [n * 48 + c] = dw[base + (size_t)(2 * NCH) * P_PIX + off];
    }
    __syncthreads();

    if (tid < 128) {
        int n = tid & 63;
        const float* src = (tid < 64) ? sq : sk2;
        float s = 0.f;
#pragma unroll
        for (int c = 0; c < CH; c++) { float v = src[n * 49 + c]; s = fmaf(v, v, s); }
        float nn = fmaxf(sqrtf(s), 1e-12f);
        if (tid < 64) nq[n] = nn; else nk[n] = nn;
    }
    __syncthreads();

    // temperature broadcast index after the reference's dim-remix: wx & 7
    const float t = temp[wx & 7];
#pragma unroll
    for (int o = 0; o < 16; o++) {
        int e = tid + o * 256;
        int n = e >> 6, m = e & 63;
        float s = 0.f;
#pragma unroll 8
        for (int c = 0; c < CH; c++) s = fmaf(sq[n * 49 + c], sk2[m * 49 + c], s);
        sat[n * 65 + m] = s / (nq[n] * nk[m]) * t;
    }
    __syncthreads();

    const int warp = tid >> 5, ln = tid & 31;
    const int KT[4] = {31, 41, 47, 50};   // rank targets for k=32,42,48,51
    float wts[4] = {w1p[0], w2p[0], w3p[0], w4p[0]};

    for (int rr = 0; rr < 8; rr++) {
        int n = warp * 8 + rr;
        float a0 = sat[n * 65 + ln];
        float a1 = sat[n * 65 + ln + 32];
        int r0 = 0, r1 = 0;
        for (int i2 = 0; i2 < NWIN; i2++) {
            float ai = sat[n * 65 + i2];
            r0 += (ai > a0) || (ai == a0 && i2 < ln);
            r1 += (ai > a1) || (ai == a1 && i2 < ln + 32);
        }
#pragma unroll
        for (int kx = 0; kx < 4; kx++) {
            if (r0 == KT[kx]) sth[n * 4 + kx] = a0;
            if (r1 == KT[kx]) sth[n * 4 + kx] = a1;
        }
        __syncwarp();

        float m = fmaxf(a0, a1);
#pragma unroll
        for (int o = 16; o; o >>= 1) m = fmaxf(m, __shfl_xor_sync(0xffffffffu, m, o));
        float e0 = expf(a0 - m), e1 = expf(a1 - m);

        float c0 = 0.f, c1 = 0.f;
#pragma unroll
        for (int kx = 0; kx < 4; kx++) {
            float th = sth[n * 4 + kx];
            float zz = (a0 >= th ? e0 : 0.f) + (a1 >= th ? e1 : 0.f);
#pragma unroll
            for (int o = 16; o; o >>= 1) zz += __shfl_xor_sync(0xffffffffu, zz, o);
            float f = wts[kx] / zz;
            if (a0 >= th) c0 += f;
            if (a1 >= th) c1 += f;
        }
        __syncwarp();
        sat[n * 65 + ln]      = e0 * c0;
        sat[n * 65 + ln + 32] = e1 * c1;
        __syncwarp();
    }
    __syncthreads();

    // out token n lands at contiguous p = wy*1024 + wx*64 + n (reference's reshape remix)
#pragma unroll
    for (int o = 0; o < 12; o++) {
        int e = tid + o * 256;
        int c = e >> 6, n = e & 63;
        float s = 0.f;
#pragma unroll 8
        for (int m = 0; m < NWIN; m++) s = fmaf(sat[n * 65 + m], sv[m * 48 + c], s);
        int p = wy * 1024 + wx * 64 + n;
        size_t oidx = ((size_t)b * NCH + head * CH + c) * P_PIX + p;
        out[oidx] += s;
    }
}

// ---------------- host launcher ----------------
extern "C" void kernel_launch(void* const* d_in, const int* in_sizes, int n_in,
                              void* d_out, int out_size)
{
    const float* x      = (const float*)d_in[0];
    const float* w_qkv  = (const float*)d_in[1];
    const float* w_dw   = (const float*)d_in[2];
    const float* w_proj = (const float*)d_in[3];
    const float* temp   = (const float*)d_in[4];
    const float* a1     = (const float*)d_in[5];
    const float* a2     = (const float*)d_in[6];
    const float* a3     = (const float*)d_in[7];
    const float* a4     = (const float*)d_in[8];
    float* out = (float*)d_out;

    float *qkv, *dwb, *sum, *cnq, *cnk, *cpart, *ccoef;
    cudaGetSymbolAddress((void**)&qkv,   g_qkv);
    cudaGetSymbolAddress((void**)&dwb,   g_dw);
    cudaGetSymbolAddress((void**)&sum,   g_sum);
    cudaGetSymbolAddress((void**)&cnq,   g_cnq);
    cudaGetSymbolAddress((void**)&cnk,   g_cnk);
    cudaGetSymbolAddress((void**)&cpart, g_cpart);
    cudaGetSymbolAddress((void**)&ccoef, g_ccoef);

    const int spatial_smem = (64*49*2 + 64*48 + 64*65 + 64 + 64 + 64*4) * 4;
    cudaFuncSetAttribute(spatial_kernel, cudaFuncAttributeMaxDynamicSharedMemorySize, 65536);

    // 1) qkv = 1x1 conv (SGEMM 1152x384x16384 x2)
    gemm1x1<<<dim3(P_PIX / 128, NQKV / 128, 2), 256>>>(w_qkv, x, qkv, NQKV, NCH);
    // 2) depthwise 3x3
    dwconv_kernel<<<(2 * NQKV * P_PIX) / 256, 256>>>(qkv, w_dw, dwb);
    // 3) channel-row norms (q, k)
    chan_norms_kernel<<<2 * 2 * NCH, 256>>>(dwb, cnq, cnk);
    // 4) cattn raw dots, split-K partials
    cattn_kernel<<<dim3(CSPLIT, 16), 256>>>(dwb, cpart);
    // 5) combined channel softmax coefficients
    chan_coef_kernel<<<96, 256>>>(cpart, cnq, cnk, temp, a1, a2, a3, a4, ccoef);
    // 6) cout = coef @ v  (writes g_sum)
    cout_kernel<<<dim3(P_PIX / 256, 16), 256>>>(ccoef, dwb, sum);
    // 7) fused spatial window attention (adds into g_sum)
    spatial_kernel<<<dim3(512, HEADS), 256, spatial_smem>>>(dwb, temp, a1, a2, a3, a4, sum);
    // 8) proj 1x1 conv -> d_out (SGEMM 384x384x16384 x2)
    gemm1x1<<<dim3(P_PIX / 128, NCH / 128, 2), 256>>>(w_proj, sum, out, NCH, NCH);
}

// round 3
// speedup vs baseline: 1.5239x; 1.0983x over previous
#include <cuda_runtime.h>
#include <math.h>

#define P_PIX 16384   // 128*128
#define NCH   384
#define NQKV  1152
#define HEADS 8
#define CH    48      // per-head channels
#define NWIN  64      // tokens per 8x8 window
#define CSPLIT 32     // cattn K splits

typedef unsigned long long u64t;

__device__ __forceinline__ u64t dup_f32(float a) {
    u64t r;
    asm("mov.b64 %0, {%1, %1};" : "=l"(r) : "f"(a));
    return r;
}
__device__ __forceinline__ void ffma2(u64t& acc, u64t a, u64t b) {
    asm("fma.rn.f32x2 %0, %1, %2, %0;" : "+l"(acc) : "l"(a), "l"(b));
}
__device__ __forceinline__ float pair_sum(u64t v) {
    float lo, hi;
    asm("mov.b64 {%0, %1}, %2;" : "=f"(lo), "=f"(hi) : "l"(v));
    return lo + hi;
}
__device__ __forceinline__ u64t pack2(float lo, float hi) {
    u64t r;
    asm("mov.b64 %0, {%1, %2};" : "=l"(r) : "f"(lo), "f"(hi));
    return r;
}

// ---------------- scratch (device globals; no allocs allowed) ----------------
__device__ float g_qkv[2ll * NQKV * P_PIX];    // after 1x1 conv
__device__ float g_dw [2ll * NQKV * P_PIX];    // after depthwise: q|k|v
__device__ float g_sum[2ll * NCH  * P_PIX];    // cout + sout (pre-proj)
__device__ float g_cnq[2 * NCH];
__device__ float g_cnk[2 * NCH];
__device__ float g_cpart[CSPLIT * 16 * CH * CH];   // split-K partials for cattn
__device__ float g_ccoef[16 * CH * CH];            // combined softmax coefficients

// ------- 1x1 conv as SGEMM: Y[b][m][p] = sum_k W[m][k] X[b][k][p] -----------
// 128x128 tile, BK=8, double-buffered, 8x8 micro-tile, packed f32x2 FMA.
__global__ __launch_bounds__(256) void gemm1x1(
    const float* __restrict__ W, const float* __restrict__ X,
    float* __restrict__ Y, int M, int K)
{
    const int b  = blockIdx.z;
    const int m0 = blockIdx.y * 128;
    const int p0 = blockIdx.x * 128;
    const float* Xb = X + (size_t)b * K * P_PIX;
    float*       Yb = Y + (size_t)b * M * P_PIX;

    __shared__ float sA[2][8][128];
    __shared__ float sB[2][8][128];

    const int tid = threadIdx.x;
    const int tr = tid >> 4;        // 0..15  (m-group)
    const int tc = tid & 15;        // 0..15  (p-group)

    const int aRow = tid >> 1;          // 0..127
    const int aK4  = (tid & 1) * 4;     // 0 or 4
    const int bK   = tid >> 5;          // 0..7
    const int bP4  = (tid & 31) * 4;    // 0..124

    const float* Aptr = &W[(size_t)(m0 + aRow) * K + aK4];
    const float* Bptr = &Xb[(size_t)bK * P_PIX + p0 + bP4];

    u64t acc2[8][4];
#pragma unroll
    for (int i = 0; i < 8; i++)
#pragma unroll
        for (int j = 0; j < 4; j++) acc2[i][j] = 0ull;

    {   // prologue
        float4 ra = *reinterpret_cast<const float4*>(Aptr);
        float4 rb = *reinterpret_cast<const float4*>(Bptr);
        sA[0][aK4 + 0][aRow] = ra.x;
        sA[0][aK4 + 1][aRow] = ra.y;
        sA[0][aK4 + 2][aRow] = ra.z;
        sA[0][aK4 + 3][aRow] = ra.w;
        *reinterpret_cast<float4*>(&sB[0][bK][bP4]) = rb;
    }
    __syncthreads();

    const int kIter = K >> 3;
    for (int t = 0; t < kIter; t++) {
        const int cb = t & 1;
        float4 ra, rb;
        if (t + 1 < kIter) {
            const int k0 = (t + 1) << 3;
            ra = *reinterpret_cast<const float4*>(Aptr + k0);
            rb = *reinterpret_cast<const float4*>(Bptr + (size_t)k0 * P_PIX);
        }
#pragma unroll
        for (int k = 0; k < 8; k++) {
            float4 a0 = *reinterpret_cast<const float4*>(&sA[cb][k][tr * 8]);
            float4 a1 = *reinterpret_cast<const float4*>(&sA[cb][k][tr * 8 + 4]);
            ulonglong2 bq0 = *reinterpret_cast<const ulonglong2*>(&sB[cb][k][tc * 8]);
            ulonglong2 bq1 = *reinterpret_cast<const ulonglong2*>(&sB[cb][k][tc * 8 + 4]);
            u64t bv[4] = {bq0.x, bq0.y, bq1.x, bq1.y};
            float av[8] = {a0.x, a0.y, a0.z, a0.w, a1.x, a1.y, a1.z, a1.w};
#pragma unroll
            for (int i = 0; i < 8; i++) {
                u64t ad = dup_f32(av[i]);
#pragma unroll
                for (int j = 0; j < 4; j++) ffma2(acc2[i][j], ad, bv[j]);
            }
        }
        if (t + 1 < kIter) {
            const int nb = cb ^ 1;
            sA[nb][aK4 + 0][aRow] = ra.x;
            sA[nb][aK4 + 1][aRow] = ra.y;
            sA[nb][aK4 + 2][aRow] = ra.z;
            sA[nb][aK4 + 3][aRow] = ra.w;
            *reinterpret_cast<float4*>(&sB[nb][bK][bP4]) = rb;
            __syncthreads();
        }
    }

#pragma unroll
    for (int i = 0; i < 8; i++) {
        const int m = m0 + tr * 8 + i;
        u64t* yp = reinterpret_cast<u64t*>(&Yb[(size_t)m * P_PIX + p0 + tc * 8]);
        *reinterpret_cast<ulonglong2*>(yp)     = make_ulonglong2(acc2[i][0], acc2[i][1]);
        *reinterpret_cast<ulonglong2*>(yp + 2) = make_ulonglong2(acc2[i][2], acc2[i][3]);
    }
}

// ---------------- depthwise 3x3, pad 1, 4 pixels/thread ----------------
__global__ __launch_bounds__(256) void dwconv_kernel(
    const float* __restrict__ in, const float* __restrict__ Wd, float* __restrict__ out)
{
    int gid = blockIdx.x * 256 + threadIdx.x;      // 2*1152*4096
    int grp = gid & 4095;
    int bc  = gid >> 12;
    int ch  = bc % NQKV;
    int x0 = (grp & 31) * 4, y = grp >> 5;
    const float* ip = in + (size_t)bc * P_PIX;
    const float* w  = Wd + ch * 9;
    float o0 = 0.f, o1 = 0.f, o2 = 0.f, o3 = 0.f;
#pragma unroll
    for (int dy = -1; dy <= 1; dy++) {
        int yy = y + dy;
        if ((unsigned)yy >= 128u) continue;
        const float* rp = ip + yy * 128;
        float v[6];
#pragma unroll
        for (int t = 0; t < 6; t++) {
            int xx = x0 - 1 + t;
            v[t] = ((unsigned)xx < 128u) ? rp[xx] : 0.f;
        }
#pragma unroll
        for (int dx = 0; dx < 3; dx++) {
            float wv = w[(dy + 1) * 3 + dx];
            o0 = fmaf(wv, v[dx + 0], o0);
            o1 = fmaf(wv, v[dx + 1], o1);
            o2 = fmaf(wv, v[dx + 2], o2);
            o3 = fmaf(wv, v[dx + 3], o3);
        }
    }
    *reinterpret_cast<float4*>(&out[(size_t)bc * P_PIX + y * 128 + x0]) =
        make_float4(o0, o1, o2, o3);
}

// ---------------- per-channel-row L2 norms over 16384 (q and k) -------------
__global__ __launch_bounds__(256) void chan_norms_kernel(
    const float* __restrict__ dw, float* __restrict__ nq, float* __restrict__ nk)
{
    int row = blockIdx.x;            // 0..1535
    int b = row / 768;
    int r = row % 768;               // 0..383 q, 384..767 k
    const float* p = dw + ((size_t)b * NQKV + r) * P_PIX;
    float s = 0.f;
    for (int i = threadIdx.x * 4; i < P_PIX; i += 1024) {
        float4 v = *reinterpret_cast<const float4*>(&p[i]);
        s = fmaf(v.x, v.x, s); s = fmaf(v.y, v.y, s);
        s = fmaf(v.z, v.z, s); s = fmaf(v.w, v.w, s);
    }
    __shared__ float red[256];
    red[threadIdx.x] = s; __syncthreads();
    for (int st = 128; st > 0; st >>= 1) {
        if (threadIdx.x < st) red[threadIdx.x] += red[threadIdx.x + st];
        __syncthreads();
    }
    if (threadIdx.x == 0) {
        float n = fmaxf(sqrtf(red[0]), 1e-12f);
        if (r < NCH) nq[b * NCH + r] = n; else nk[b * NCH + (r - NCH)] = n;
    }
}

// ------ cattn raw dots, split-K partials, 3x3 register tiling ---------------
__global__ __launch_bounds__(256) void cattn_kernel(
    const float* __restrict__ dw, float* __restrict__ part)
{
    const int bh = blockIdx.y;             // b*8+h (0..15)
    const int b = bh >> 3, h = bh & 7;
    const int kbase = blockIdx.x * (P_PIX / CSPLIT);   // 512 positions per split
    const float* qb = dw + ((size_t)b * NQKV + h * CH) * P_PIX;
    const float* kb = dw + ((size_t)b * NQKV + NCH + h * CH) * P_PIX;

    __shared__ float sq[CH][65];
    __shared__ float sk[CH][65];

    const int tid = threadIdx.x;
    const int ti = tid >> 4, tj = tid & 15;
    const int i0 = ti * 3, j0 = tj * 3;

    float acc[3][3];
#pragma unroll
    for (int r = 0; r < 3; r++)
#pragma unroll
        for (int c = 0; c < 3; c++) acc[r][c] = 0.f;

    for (int kc = 0; kc < P_PIX / CSPLIT; kc += 64) {
        const int kpos = kbase + kc;
        for (int e = tid; e < CH * 16; e += 256) {     // float4 loads
            int r = e >> 4, c4 = (e & 15) * 4;
            float4 vq = *reinterpret_cast<const float4*>(&qb[(size_t)r * P_PIX + kpos + c4]);
            float4 vk = *reinterpret_cast<const float4*>(&kb[(size_t)r * P_PIX + kpos + c4]);
            sq[r][c4] = vq.x; sq[r][c4+1] = vq.y; sq[r][c4+2] = vq.z; sq[r][c4+3] = vq.w;
            sk[r][c4] = vk.x; sk[r][c4+1] = vk.y; sk[r][c4+2] = vk.z; sk[r][c4+3] = vk.w;
        }
        __syncthreads();
#pragma unroll 8
        for (int kk = 0; kk < 64; kk++) {
            float a0 = sq[i0][kk], a1 = sq[i0+1][kk], a2 = sq[i0+2][kk];
            float b0 = sk[j0][kk], b1 = sk[j0+1][kk], b2 = sk[j0+2][kk];
            acc[0][0] = fmaf(a0, b0, acc[0][0]);
            acc[0][1] = fmaf(a0, b1, acc[0][1]);
            acc[0][2] = fmaf(a0, b2, acc[0][2]);
            acc[1][0] = fmaf(a1, b0, acc[1][0]);
            acc[1][1] = fmaf(a1, b1, acc[1][1]);
            acc[1][2] = fmaf(a1, b2, acc[1][2]);
            acc[2][0] = fmaf(a2, b0, acc[2][0]);
            acc[2][1] = fmaf(a2, b1, acc[2][1]);
            acc[2][2] = fmaf(a2, b2, acc[2][2]);
        }
        __syncthreads();
    }
    float* pr = &part[((size_t)blockIdx.x * 16 + bh) * (CH * CH)];
#pragma unroll
    for (int r = 0; r < 3; r++)
#pragma unroll
        for (int c = 0; c < 3; c++)
            pr[(i0 + r) * CH + (j0 + c)] = acc[r][c];
}

// ------- channel branch: combined top-k softmax coefficients (one warp/row) --
__global__ __launch_bounds__(256) void chan_coef_kernel(
    const float* __restrict__ part, const float* __restrict__ nq,
    const float* __restrict__ nk, const float* __restrict__ temp,
    const float* __restrict__ w1p, const float* __restrict__ w2p,
    const float* __restrict__ w3p, const float* __restrict__ w4p,
    float* __restrict__ coef)
{
    const int warp = threadIdx.x >> 5, ln = threadIdx.x & 31;
    const int row = blockIdx.x * 8 + warp;     // (b*8+h)*48 + i, 0..767
    const int bh = row / CH, i = row % CH;
    const int b = bh >> 3, h = bh & 7;
    const float t = temp[h];
    const float inq = 1.f / nq[b * NCH + h * CH + i];
    const int KT[4] = {23, 31, 35, 37};        // rank targets (k-1) for k=24,32,36,38
    float wts[4] = {w1p[0], w2p[0], w3p[0], w4p[0]};

    __shared__ float sa[8][CH];
    __shared__ float sth[8][4];

    int j0 = ln, j1 = ln + 32;
    float d0 = 0.f, d1 = 0.f;
    for (int s = 0; s < CSPLIT; s++) {
        const float* pr = part + ((size_t)s * 16 + bh) * (CH * CH) + i * CH;
        d0 += pr[j0];
        if (j1 < CH) d1 += pr[j1];
    }
    float a0 = d0 * inq / nk[b * NCH + h * CH + j0] * t;
    float a1 = (j1 < CH) ? d1 * inq / nk[b * NCH + h * CH + j1] * t : -INFINITY;
    sa[warp][j0] = a0;
    if (j1 < CH) sa[warp][j1] = a1;
    __syncwarp();

    int r0 = 0, r1 = 0;
    for (int q = 0; q < CH; q++) {
        float aq = sa[warp][q];
        r0 += (aq > a0) || (aq == a0 && q < j0);
        if (j1 < CH) r1 += (aq > a1) || (aq == a1 && q < j1);
    }
#pragma unroll
    for (int kx = 0; kx < 4; kx++) {
        if (r0 == KT[kx]) sth[warp][kx] = a0;
        if (j1 < CH && r1 == KT[kx]) sth[warp][kx] = a1;
    }
    __syncwarp();

    float m = fmaxf(a0, a1);
#pragma unroll
    for (int o = 16; o; o >>= 1) m = fmaxf(m, __shfl_xor_sync(0xffffffffu, m, o));
    float e0 = expf(a0 - m);
    float e1 = (j1 < CH) ? expf(a1 - m) : 0.f;

    float c0 = 0.f, c1 = 0.f;
#pragma unroll
    for (int kx = 0; kx < 4; kx++) {
        float th = sth[warp][kx];
        float zz = (a0 >= th ? e0 : 0.f) + ((j1 < CH && a1 >= th) ? e1 : 0.f);
#pragma unroll
        for (int o = 16; o; o >>= 1) zz += __shfl_xor_sync(0xffffffffu, zz, o);
        float f = wts[kx] / zz;
        if (a0 >= th) c0 += f;
        if (j1 < CH && a1 >= th) c1 += f;
    }
    coef[row * CH + j0] = e0 * c0;
    if (j1 < CH) coef[row * CH + j1] = e1 * c1;
}

// ------- cout = coef @ vc, packed i-pairs, broadcast shared loads -----------
__global__ __launch_bounds__(256) void cout_kernel(
    const float* __restrict__ coef, const float* __restrict__ dw,
    float* __restrict__ out)
{
    int bh = blockIdx.y; int b = bh >> 3, h = bh & 7;
    int p = blockIdx.x * 256 + threadIdx.x;
    __shared__ u64t scp[CH][CH / 2];    // scp[j][i2] = {coef[2*i2][j], coef[2*i2+1][j]}
    const float* cf = coef + bh * CH * CH;
    for (int e = threadIdx.x; e < CH * (CH / 2); e += 256) {
        int j = e / (CH / 2), i2 = e % (CH / 2);
        scp[j][i2] = pack2(cf[(2 * i2) * CH + j], cf[(2 * i2 + 1) * CH + j]);
    }
    __syncthreads();
    const float* vb = dw + ((size_t)b * NQKV + 2 * NCH + h * CH) * P_PIX + p;
    u64t acc2[CH / 2];
#pragma unroll
    for (int i = 0; i < CH / 2; i++) acc2[i] = 0ull;
    for (int j = 0; j < CH; j++) {
        u64t vd = dup_f32(vb[(size_t)j * P_PIX]);
#pragma unroll
        for (int i = 0; i < CH / 2; i++) ffma2(acc2[i], vd, scp[j][i]);
    }
    float* ob = out + ((size_t)b * NCH + h * CH) * P_PIX + p;
#pragma unroll
    for (int i = 0; i < CH / 2; i++) {
        float lo, hi;
        asm("mov.b64 {%0, %1}, %2;" : "=f"(lo), "=f"(hi) : "l"(acc2[i]));
        ob[(size_t)(2 * i) * P_PIX]     = lo;
        ob[(size_t)(2 * i + 1) * P_PIX] = hi;
    }
}

// ---------------- fused spatial window attention (f32x2 math) ----------------
#define SQ_STR 50
#define SAT_STR 66
__global__ __launch_bounds__(256) void spatial_kernel(
    const float* __restrict__ dw, const float* __restrict__ temp,
    const float* __restrict__ w1p, const float* __restrict__ w2p,
    const float* __restrict__ w3p, const float* __restrict__ w4p,
    float* __restrict__ out)
{
    extern __shared__ float smem[];
    float* sq  = smem;                       // 64*50
    float* sk2 = sq  + 64 * SQ_STR;          // 64*50
    float* svT = sk2 + 64 * SQ_STR;          // 48*66  (transposed: svT[c][m])
    float* sat = svT + 48 * SAT_STR;         // 64*66
    float* nq  = sat + 64 * SAT_STR;         // 64
    float* nk  = nq  + 64;                   // 64
    float* sth = nk  + 64;                   // 64*4

    const int win = blockIdx.x;                  // 0..511
    const int head = blockIdx.y;                 // 0..7
    const int b = win >> 8, wy = (win >> 4) & 15, wx = win & 15;
    const int tid = threadIdx.x;

    const size_t base = ((size_t)b * NQKV + head * CH) * P_PIX + (size_t)(wy * 8) * 128 + wx * 8;

    for (int e = tid; e < NWIN * CH; e += 256) {
        int c = e >> 6, n = e & 63;
        int iy = n >> 3, ix = n & 7;
        size_t off = (size_t)c * P_PIX + iy * 128 + ix;
        sq [n * SQ_STR + c] = dw[base + off];
        sk2[n * SQ_STR + c] = dw[base + (size_t)NCH * P_PIX + off];
        svT[c * SAT_STR + n] = dw[base + (size_t)(2 * NCH) * P_PIX + off];
    }
    __syncthreads();

    if (tid < 128) {
        int n = tid & 63;
        const float* src = (tid < 64) ? sq : sk2;
        float s = 0.f;
#pragma unroll
        for (int c = 0; c < CH; c++) { float v = src[n * SQ_STR + c]; s = fmaf(v, v, s); }
        float nn = fmaxf(sqrtf(s), 1e-12f);
        if (tid < 64) nq[n] = nn; else nk[n] = nn;
    }
    __syncthreads();

    // temperature broadcast index after the reference's dim-remix: wx & 7
    const float t = temp[wx & 7];
#pragma unroll
    for (int o = 0; o < 16; o++) {
        int e = tid + o * 256;
        int n = e >> 6, m = e & 63;
        const u64t* qp = reinterpret_cast<const u64t*>(&sq[n * SQ_STR]);
        const u64t* kp = reinterpret_cast<const u64t*>(&sk2[m * SQ_STR]);
        u64t s2 = 0ull;
#pragma unroll
        for (int c2 = 0; c2 < CH / 2; c2++) ffma2(s2, qp[c2], kp[c2]);
        sat[n * SAT_STR + m] = pair_sum(s2) / (nq[n] * nk[m]) * t;
    }
    __syncthreads();

    const int warp = tid >> 5, ln = tid & 31;
    const int KT[4] = {31, 41, 47, 50};   // rank targets for k=32,42,48,51
    float wts[4] = {w1p[0], w2p[0], w3p[0], w4p[0]};

    for (int rr = 0; rr < 8; rr++) {
        int n = warp * 8 + rr;
        float a0 = sat[n * SAT_STR + ln];
        float a1 = sat[n * SAT_STR + ln + 32];
        int r0 = 0, r1 = 0;
        for (int i2 = 0; i2 < NWIN; i2++) {
            float ai = sat[n * SAT_STR + i2];
            r0 += (ai > a0) || (ai == a0 && i2 < ln);
            r1 += (ai > a1) || (ai == a1 && i2 < ln + 32);
        }
#pragma unroll
        for (int kx = 0; kx < 4; kx++) {
            if (r0 == KT[kx]) sth[n * 4 + kx] = a0;
            if (r1 == KT[kx]) sth[n * 4 + kx] = a1;
        }
        __syncwarp();

        float m = fmaxf(a0, a1);
#pragma unroll
        for (int o = 16; o; o >>= 1) m = fmaxf(m, __shfl_xor_sync(0xffffffffu, m, o));
        float e0 = expf(a0 - m), e1 = expf(a1 - m);

        float c0 = 0.f, c1 = 0.f;
#pragma unroll
        for (int kx = 0; kx < 4; kx++) {
            float th = sth[n * 4 + kx];
            float zz = (a0 >= th ? e0 : 0.f) + (a1 >= th ? e1 : 0.f);
#pragma unroll
            for (int o = 16; o; o >>= 1) zz += __shfl_xor_sync(0xffffffffu, zz, o);
            float f = wts[kx] / zz;
            if (a0 >= th) c0 += f;
            if (a1 >= th) c1 += f;
        }
        __syncwarp();
        sat[n * SAT_STR + ln]      = e0 * c0;
        sat[n * SAT_STR + ln + 32] = e1 * c1;
        __syncwarp();
    }
    __syncthreads();

    // out token n lands at contiguous p = wy*1024 + wx*64 + n (reference's reshape remix)
#pragma unroll
    for (int o = 0; o < 12; o++) {
        int e = tid + o * 256;
        int c = e >> 6, n = e & 63;
        const u64t* ap = reinterpret_cast<const u64t*>(&sat[n * SAT_STR]);
        const u64t* vp = reinterpret_cast<const u64t*>(&svT[c * SAT_STR]);
        u64t s2 = 0ull;
#pragma unroll
        for (int m2 = 0; m2 < NWIN / 2; m2++) ffma2(s2, ap[m2], vp[m2]);
        int p = wy * 1024 + wx * 64 + n;
        size_t oidx = ((size_t)b * NCH + head * CH + c) * P_PIX + p;
        out[oidx] += pair_sum(s2);
    }
}

// ---------------- host launcher ----------------
extern "C" void kernel_launch(void* const* d_in, const int* in_sizes, int n_in,
                              void* d_out, int out_size)
{
    const float* x      = (const float*)d_in[0];
    const float* w_qkv  = (const float*)d_in[1];
    const float* w_dw   = (const float*)d_in[2];
    const float* w_proj = (const float*)d_in[3];
    const float* temp   = (const float*)d_in[4];
    const float* a1     = (const float*)d_in[5];
    const float* a2     = (const float*)d_in[6];
    const float* a3     = (const float*)d_in[7];
    const float* a4     = (const float*)d_in[8];
    float* out = (float*)d_out;

    float *qkv, *dwb, *sum, *cnq, *cnk, *cpart, *ccoef;
    cudaGetSymbolAddress((void**)&qkv,   g_qkv);
    cudaGetSymbolAddress((void**)&dwb,   g_dw);
    cudaGetSymbolAddress((void**)&sum,   g_sum);
    cudaGetSymbolAddress((void**)&cnq,   g_cnq);
    cudaGetSymbolAddress((void**)&cnk,   g_cnk);
    cudaGetSymbolAddress((void**)&cpart, g_cpart);
    cudaGetSymbolAddress((void**)&ccoef, g_ccoef);

    const int spatial_smem =
        (64 * SQ_STR * 2 + 48 * SAT_STR + 64 * SAT_STR + 64 + 64 + 64 * 4) * 4;
    cudaFuncSetAttribute(spatial_kernel, cudaFuncAttributeMaxDynamicSharedMemorySize, 65536);

    // 1) qkv = 1x1 conv (SGEMM 1152x384x16384 x2)
    gemm1x1<<<dim3(P_PIX / 128, NQKV / 128, 2), 256>>>(w_qkv, x, qkv, NQKV, NCH);
    // 2) depthwise 3x3
    dwconv_kernel<<<(2 * NQKV * P_PIX / 4) / 256, 256>>>(qkv, w_dw, dwb);
    // 3) channel-row norms (q, k)
    chan_norms_kernel<<<2 * 2 * NCH, 256>>>(dwb, cnq, cnk);
    // 4) cattn raw dots, split-K partials
    cattn_kernel<<<dim3(CSPLIT, 16), 256>>>(dwb, cpart);
    // 5) combined channel softmax coefficients
    chan_coef_kernel<<<96, 256>>>(cpart, cnq, cnk, temp, a1, a2, a3, a4, ccoef);
    // 6) cout = coef @ v  (writes g_sum)
    cout_kernel<<<dim3(P_PIX / 256, 16), 256>>>(ccoef, dwb, sum);
    // 7) fused spatial window attention (adds into g_sum)
    spatial_kernel<<<dim3(512, HEADS), 256, spatial_smem>>>(dwb, temp, a1, a2, a3, a4, sum);
    // 8) proj 1x1 conv -> d_out (SGEMM 384x384x16384 x2)
    gemm1x1<<<dim3(P_PIX / 128, NCH / 128, 2), 256>>>(w_proj, sum, out, NCH, NCH);
}

// round 6
// speedup vs baseline: 2.0926x; 1.3732x over previous
#include <cuda_runtime.h>
#include <cuda_bf16.h>
#include <math.h>
#include <cstdint>

#define P_PIX 16384   // 128*128
#define NCH   384
#define NQKV  1152
#define HEADS 8
#define CH    48      // per-head channels
#define NWIN  64      // tokens per 8x8 window
#define CSPLIT 32     // cattn K splits
#define GK    384     // GEMM K (both gemms)
#define BK    64      // K chunk
#define A_STR 72      // smem row stride (bf16 elems), conflict-free for ldmatrix

typedef unsigned long long u64t;

__device__ __forceinline__ u64t dup_f32(float a) {
    u64t r; asm("mov.b64 %0, {%1, %1};" : "=l"(r) : "f"(a)); return r;
}
__device__ __forceinline__ void ffma2(u64t& acc, u64t a, u64t b) {
    asm("fma.rn.f32x2 %0, %1, %2, %0;" : "+l"(acc) : "l"(a), "l"(b));
}
__device__ __forceinline__ float pair_sum(u64t v) {
    float lo, hi; asm("mov.b64 {%0, %1}, %2;" : "=f"(lo), "=f"(hi) : "l"(v)); return lo + hi;
}
__device__ __forceinline__ u64t pack2(float lo, float hi) {
    u64t r; asm("mov.b64 %0, {%1, %2};" : "=l"(r) : "f"(lo), "f"(hi)); return r;
}
__device__ __forceinline__ uint32_t smem_u32(const void* p) {
    uint32_t a;
    asm("{ .reg .u64 t; cvta.to.shared.u64 t, %1; cvt.u32.u64 %0, t; }" : "=r"(a) : "l"(p));
    return a;
}
__device__ __forceinline__ void ldsm_x4(uint32_t* r, uint32_t addr) {
    asm volatile("ldmatrix.sync.aligned.m8n8.x4.shared.b16 {%0,%1,%2,%3}, [%4];"
                 : "=r"(r[0]), "=r"(r[1]), "=r"(r[2]), "=r"(r[3]) : "r"(addr));
}
__device__ __forceinline__ void ldsm_x2(uint32_t* r, uint32_t addr) {
    asm volatile("ldmatrix.sync.aligned.m8n8.x2.shared.b16 {%0,%1}, [%2];"
                 : "=r"(r[0]), "=r"(r[1]) : "r"(addr));
}
__device__ __forceinline__ void mma_bf16(float* c, const uint32_t* a, const uint32_t* b) {
    asm volatile("mma.sync.aligned.m16n8k16.row.col.f32.bf16.bf16.f32 "
                 "{%0,%1,%2,%3}, {%4,%5,%6,%7}, {%8,%9}, {%0,%1,%2,%3};"
                 : "+f"(c[0]), "+f"(c[1]), "+f"(c[2]), "+f"(c[3])
                 : "r"(a[0]), "r"(a[1]), "r"(a[2]), "r"(a[3]), "r"(b[0]), "r"(b[1]));
}

// ---------------- scratch (device globals; no allocs allowed) ----------------
__device__ float g_qkv[2ll * NQKV * P_PIX];    // after 1x1 conv (fp32)
__device__ float g_dw [2ll * NQKV * P_PIX];    // after depthwise: q|k|v
__device__ float g_sum[2ll * NCH  * P_PIX];    // cout + sout (pre-proj)
__device__ float g_cnq[2 * NCH];
__device__ float g_cnk[2 * NCH];
__device__ float g_cpart[CSPLIT * 16 * CH * CH];
__device__ float g_ccoef[16 * CH * CH];
__device__ __nv_bfloat16 g_xth[2ll * P_PIX * GK];  // X^T hi  [b][p][k]
__device__ __nv_bfloat16 g_xtl[2ll * P_PIX * GK];  // X^T lo
__device__ __nv_bfloat16 g_wqh[NQKV * NCH];
__device__ __nv_bfloat16 g_wql[NQKV * NCH];
__device__ __nv_bfloat16 g_wph[NCH * NCH];
__device__ __nv_bfloat16 g_wpl[NCH * NCH];

// ---------------- weight split fp32 -> bf16 hi/lo ----------------
__global__ __launch_bounds__(256) void convert_w(
    const float* __restrict__ W, __nv_bfloat16* __restrict__ Wh,
    __nv_bfloat16* __restrict__ Wl, int n)
{
    int i = blockIdx.x * 256 + threadIdx.x;
    if (i >= n) return;
    float v = W[i];
    __nv_bfloat16 hi = __float2bfloat16(v);
    Wh[i] = hi;
    Wl[i] = __float2bfloat16(v - __bfloat162float(hi));
}

// ------- transpose+split: X fp32 [b][K=384][16384] -> T bf16 [b][16384][384] --
__global__ __launch_bounds__(256) void transpose_split(
    const float* __restrict__ X, __nv_bfloat16* __restrict__ Th,
    __nv_bfloat16* __restrict__ Tl)
{
    __shared__ float s[32][33];
    const int b  = blockIdx.z;
    const int p0 = blockIdx.x * 32;
    const int k0 = blockIdx.y * 32;
    const int tid = threadIdx.x;
    const int tx = tid & 31, ty = tid >> 5;
    const float* Xb = X + ((size_t)b * GK + k0) * P_PIX + p0;
#pragma unroll
    for (int i = 0; i < 4; i++)
        s[ty + 8 * i][tx] = Xb[(size_t)(ty + 8 * i) * P_PIX + tx];
    __syncthreads();
    const int row = tid >> 3;            // 0..31 (pixel within tile)
    const int kk = (tid & 7) * 4;        // 0..28
    __nv_bfloat16 hv[4], lv[4];
#pragma unroll
    for (int j = 0; j < 4; j++) {
        float v = s[kk + j][row];
        hv[j] = __float2bfloat16(v);
        lv[j] = __float2bfloat16(v - __bfloat162float(hv[j]));
    }
    size_t ob = ((size_t)b * P_PIX + p0 + row) * GK + k0 + kk;
    *reinterpret_cast<__nv_bfloat162*>(&Th[ob])     = *reinterpret_cast<__nv_bfloat162*>(&hv[0]);
    *reinterpret_cast<__nv_bfloat162*>(&Th[ob + 2]) = *reinterpret_cast<__nv_bfloat162*>(&hv[2]);
    *reinterpret_cast<__nv_bfloat162*>(&Tl[ob])     = *reinterpret_cast<__nv_bfloat162*>(&lv[0]);
    *reinterpret_cast<__nv_bfloat162*>(&Tl[ob + 2]) = *reinterpret_cast<__nv_bfloat162*>(&lv[2]);
}

// ------------- split-bf16 HMMA GEMM: Y[b][m][p] = sum_k W[m][k] X[k][p] ------
// A = W (hi/lo, row-major [m][k]); B = X^T (hi/lo, row-major [p][k]).
// CTA tile 128x128, 8 warps (2x4), warp tile 64x32, BK=64 single-buffered.
__global__ __launch_bounds__(256, 2) void hmma_gemm(
    const __nv_bfloat16* __restrict__ Wh, const __nv_bfloat16* __restrict__ Wl,
    const __nv_bfloat16* __restrict__ Th, const __nv_bfloat16* __restrict__ Tl,
    float* __restrict__ Y, int M)
{
    extern __shared__ __nv_bfloat16 sm[];
    __nv_bfloat16* sAh = sm;
    __nv_bfloat16* sAl = sm + 128 * A_STR;
    __nv_bfloat16* sBh = sm + 2 * 128 * A_STR;
    __nv_bfloat16* sBl = sm + 3 * 128 * A_STR;

    const int tid = threadIdx.x;
    const int wid = tid >> 5, lane = tid & 31;
    const int wr = wid >> 2;          // 0..1
    const int wc = wid & 3;           // 0..3
    const int b  = blockIdx.z;
    const int m0 = blockIdx.y * 128;
    const int p0 = blockIdx.x * 128;

    const __nv_bfloat16* gAh = Wh + (size_t)m0 * GK;
    const __nv_bfloat16* gAl = Wl + (size_t)m0 * GK;
    const __nv_bfloat16* gBh = Th + ((size_t)b * P_PIX + p0) * GK;
    const __nv_bfloat16* gBl = Tl + ((size_t)b * P_PIX + p0) * GK;

    float acc[4][4][4];
#pragma unroll
    for (int i = 0; i < 4; i++)
#pragma unroll
        for (int j = 0; j < 4; j++)
#pragma unroll
            for (int r = 0; r < 4; r++) acc[i][j][r] = 0.f;

    // per-thread load slots: idx in [0,1024): row=idx>>3, c8=idx&7 (uint4 = 8 bf16)
    const uint32_t sAh32 = smem_u32(sAh);
    const uint32_t sAl32 = smem_u32(sAl);
    const uint32_t sBh32 = smem_u32(sBh);
    const uint32_t sBl32 = smem_u32(sBl);

    for (int kc = 0; kc < GK / BK; kc++) {
        const int kb = kc * BK;
        // cooperative load: 4 arrays x 1024 uint4
#pragma unroll
        for (int i = 0; i < 4; i++) {
            int idx = tid + i * 256;
            int row = idx >> 3, c8 = (idx & 7) * 8;
            size_t goff = (size_t)row * GK + kb + c8;
            uint32_t soff = (uint32_t)(row * A_STR + c8) * 2;
            *reinterpret_cast<uint4*>((char*)sAh + soff) = *reinterpret_cast<const uint4*>(gAh + goff);
            *reinterpret_cast<uint4*>((char*)sAl + soff) = *reinterpret_cast<const uint4*>(gAl + goff);
            *reinterpret_cast<uint4*>((char*)sBh + soff) = *reinterpret_cast<const uint4*>(gBh + goff);
            *reinterpret_cast<uint4*>((char*)sBl + soff) = *reinterpret_cast<const uint4*>(gBl + goff);
        }
        __syncthreads();

#pragma unroll
        for (int ks = 0; ks < BK / 16; ks++) {
            const int k0 = ks * 16;
            // B fragments: 4 n-tiles, hi & lo
            uint32_t bH[4][2], bL[4][2];
            {
                int nrow = wc * 32 + (lane & 7);
                int ncol = k0 + ((lane >> 3) & 1) * 8;
#pragma unroll
                for (int nt = 0; nt < 4; nt++) {
                    uint32_t off = (uint32_t)((nrow + nt * 8) * A_STR + ncol) * 2;
                    ldsm_x2(bH[nt], sBh32 + off);
                    ldsm_x2(bL[nt], sBl32 + off);
                }
            }
            // A hi fragments: 4 m-tiles
            {
                int arow = wr * 64 + (lane & 15);
                int acol = k0 + (lane >> 4) * 8;
                uint32_t aH[4][4];
#pragma unroll
                for (int mt = 0; mt < 4; mt++)
                    ldsm_x4(aH[mt], sAh32 + (uint32_t)((arow + mt * 16) * A_STR + acol) * 2);
#pragma unroll
                for (int mt = 0; mt < 4; mt++)
#pragma unroll
                    for (int nt = 0; nt < 4; nt++) {
                        mma_bf16(acc[mt][nt], aH[mt], bH[nt]);
                        mma_bf16(acc[mt][nt], aH[mt], bL[nt]);
                    }
                // A lo fragments (reuse registers after aH dead)
                uint32_t aL[4][4];
#pragma unroll
                for (int mt = 0; mt < 4; mt++)
                    ldsm_x4(aL[mt], sAl32 + (uint32_t)((arow + mt * 16) * A_STR + acol) * 2);
#pragma unroll
                for (int mt = 0; mt < 4; mt++)
#pragma unroll
                    for (int nt = 0; nt < 4; nt++)
                        mma_bf16(acc[mt][nt], aL[mt], bH[nt]);
            }
        }
        __syncthreads();
    }

    // epilogue: direct float2 stores
    const int tq = lane >> 2;        // 0..7 (row within 8)
    const int tr4 = lane & 3;        // 0..3
#pragma unroll
    for (int mt = 0; mt < 4; mt++) {
#pragma unroll
        for (int nt = 0; nt < 4; nt++) {
            int m  = m0 + wr * 64 + mt * 16 + tq;
            int p  = p0 + wc * 32 + nt * 8 + tr4 * 2;
            float* y0 = &Y[((size_t)b * M + m) * P_PIX + p];
            *reinterpret_cast<float2*>(y0) = make_float2(acc[mt][nt][0], acc[mt][nt][1]);
            float* y1 = &Y[((size_t)b * M + m + 8) * P_PIX + p];
            *reinterpret_cast<float2*>(y1) = make_float2(acc[mt][nt][2], acc[mt][nt][3]);
        }
    }
}

// ---------------- depthwise 3x3, pad 1, 4 pixels/thread ----------------
__global__ __launch_bounds__(256) void dwconv_kernel(
    const float* __restrict__ in, const float* __restrict__ Wd, float* __restrict__ out)
{
    int gid = blockIdx.x * 256 + threadIdx.x;      // 2*1152*4096
    int grp = gid & 4095;
    int bc  = gid >> 12;
    int ch  = bc % NQKV;
    int x0 = (grp & 31) * 4, y = grp >> 5;
    const float* ip = in + (size_t)bc * P_PIX;
    const float* w  = Wd + ch * 9;
    float o0 = 0.f, o1 = 0.f, o2 = 0.f, o3 = 0.f;
#pragma unroll
    for (int dy = -1; dy <= 1; dy++) {
        int yy = y + dy;
        if ((unsigned)yy >= 128u) continue;
        const float* rp = ip + yy * 128;
        float v[6];
#pragma unroll
        for (int t = 0; t < 6; t++) {
            int xx = x0 - 1 + t;
            v[t] = ((unsigned)xx < 128u) ? rp[xx] : 0.f;
        }
#pragma unroll
        for (int dx = 0; dx < 3; dx++) {
            float wv = w[(dy + 1) * 3 + dx];
            o0 = fmaf(wv, v[dx + 0], o0);
            o1 = fmaf(wv, v[dx + 1], o1);
            o2 = fmaf(wv, v[dx + 2], o2);
            o3 = fmaf(wv, v[dx + 3], o3);
        }
    }
    *reinterpret_cast<float4*>(&out[(size_t)bc * P_PIX + y * 128 + x0]) =
        make_float4(o0, o1, o2, o3);
}

// ---------------- per-channel-row L2 norms over 16384 (q and k) -------------
__global__ __launch_bounds__(256) void chan_norms_kernel(
    const float* __restrict__ dw, float* __restrict__ nq, float* __restrict__ nk)
{
    int row = blockIdx.x;            // 0..1535
    int b = row / 768;
    int r = row % 768;               // 0..383 q, 384..767 k
    const float* p = dw + ((size_t)b * NQKV + r) * P_PIX;
    float s = 0.f;
    for (int i = threadIdx.x * 4; i < P_PIX; i += 1024) {
        float4 v = *reinterpret_cast<const float4*>(&p[i]);
        s = fmaf(v.x, v.x, s); s = fmaf(v.y, v.y, s);
        s = fmaf(v.z, v.z, s); s = fmaf(v.w, v.w, s);
    }
    __shared__ float red[256];
    red[threadIdx.x] = s; __syncthreads();
    for (int st = 128; st > 0; st >>= 1) {
        if (threadIdx.x < st) red[threadIdx.x] += red[threadIdx.x + st];
        __syncthreads();
    }
    if (threadIdx.x == 0) {
        float n = fmaxf(sqrtf(red[0]), 1e-12f);
        if (r < NCH) nq[b * NCH + r] = n; else nk[b * NCH + (r - NCH)] = n;
    }
}

// ------ cattn raw dots, split-K partials, 3x3 register tiling ---------------
__global__ __launch_bounds__(256) void cattn_kernel(
    const float* __restrict__ dw, float* __restrict__ part)
{
    const int bh = blockIdx.y;             // b*8+h (0..15)
    const int b = bh >> 3, h = bh & 7;
    const int kbase = blockIdx.x * (P_PIX / CSPLIT);
    const float* qb = dw + ((size_t)b * NQKV + h * CH) * P_PIX;
    const float* kb = dw + ((size_t)b * NQKV + NCH + h * CH) * P_PIX;

    __shared__ float sq[CH][65];
    __shared__ float sk[CH][65];

    const int tid = threadIdx.x;
    const int ti = tid >> 4, tj = tid & 15;
    const int i0 = ti * 3, j0 = tj * 3;

    float acc[3][3];
#pragma unroll
    for (int r = 0; r < 3; r++)
#pragma unroll
        for (int c = 0; c < 3; c++) acc[r][c] = 0.f;

    for (int kc = 0; kc < P_PIX / CSPLIT; kc += 64) {
        const int kpos = kbase + kc;
        for (int e = tid; e < CH * 16; e += 256) {
            int r = e >> 4, c4 = (e & 15) * 4;
            float4 vq = *reinterpret_cast<const float4*>(&qb[(size_t)r * P_PIX + kpos + c4]);
            float4 vk = *reinterpret_cast<const float4*>(&kb[(size_t)r * P_PIX + kpos + c4]);
            sq[r][c4] = vq.x; sq[r][c4+1] = vq.y; sq[r][c4+2] = vq.z; sq[r][c4+3] = vq.w;
            sk[r][c4] = vk.x; sk[r][c4+1] = vk.y; sk[r][c4+2] = vk.z; sk[r][c4+3] = vk.w;
        }
        __syncthreads();
#pragma unroll 8
        for (int kk = 0; kk < 64; kk++) {
            float a0 = sq[i0][kk], a1 = sq[i0+1][kk], a2 = sq[i0+2][kk];
            float b0 = sk[j0][kk], b1 = sk[j0+1][kk], b2 = sk[j0+2][kk];
            acc[0][0] = fmaf(a0, b0, acc[0][0]);
            acc[0][1] = fmaf(a0, b1, acc[0][1]);
            acc[0][2] = fmaf(a0, b2, acc[0][2]);
            acc[1][0] = fmaf(a1, b0, acc[1][0]);
            acc[1][1] = fmaf(a1, b1, acc[1][1]);
            acc[1][2] = fmaf(a1, b2, acc[1][2]);
            acc[2][0] = fmaf(a2, b0, acc[2][0]);
            acc[2][1] = fmaf(a2, b1, acc[2][1]);
            acc[2][2] = fmaf(a2, b2, acc[2][2]);
        }
        __syncthreads();
    }
    float* pr = &part[((size_t)blockIdx.x * 16 + bh) * (CH * CH)];
#pragma unroll
    for (int r = 0; r < 3; r++)
#pragma unroll
        for (int c = 0; c < 3; c++)
            pr[(i0 + r) * CH + (j0 + c)] = acc[r][c];
}

// ------- channel branch: combined top-k softmax coefficients ----------------
__global__ __launch_bounds__(256) void chan_coef_kernel(
    const float* __restrict__ part, const float* __restrict__ nq,
    const float* __restrict__ nk, const float* __restrict__ temp,
    const float* __restrict__ w1p, const float* __restrict__ w2p,
    const float* __restrict__ w3p, const float* __restrict__ w4p,
    float* __restrict__ coef)
{
    const int warp = threadIdx.x >> 5, ln = threadIdx.x & 31;
    const int row = blockIdx.x * 8 + warp;
    const int bh = row / CH, i = row % CH;
    const int b = bh >> 3, h = bh & 7;
    const float t = temp[h];
    const float inq = 1.f / nq[b * NCH + h * CH + i];
    const int KT[4] = {23, 31, 35, 37};
    float wts[4] = {w1p[0], w2p[0], w3p[0], w4p[0]};

    __shared__ float sa[8][CH];
    __shared__ float sth[8][4];

    int j0 = ln, j1 = ln + 32;
    float d0 = 0.f, d1 = 0.f;
    for (int s = 0; s < CSPLIT; s++) {
        const float* pr = part + ((size_t)s * 16 + bh) * (CH * CH) + i * CH;
        d0 += pr[j0];
        if (j1 < CH) d1 += pr[j1];
    }
    float a0 = d0 * inq / nk[b * NCH + h * CH + j0] * t;
    float a1 = (j1 < CH) ? d1 * inq / nk[b * NCH + h * CH + j1] * t : -INFINITY;
    sa[warp][j0] = a0;
    if (j1 < CH) sa[warp][j1] = a1;
    __syncwarp();

    int r0 = 0, r1 = 0;
    for (int q = 0; q < CH; q++) {
        float aq = sa[warp][q];
        r0 += (aq > a0) || (aq == a0 && q < j0);
        if (j1 < CH) r1 += (aq > a1) || (aq == a1 && q < j1);
    }
#pragma unroll
    for (int kx = 0; kx < 4; kx++) {
        if (r0 == KT[kx]) sth[warp][kx] = a0;
        if (j1 < CH && r1 == KT[kx]) sth[warp][kx] = a1;
    }
    __syncwarp();

    float m = fmaxf(a0, a1);
#pragma unroll
    for (int o = 16; o; o >>= 1) m = fmaxf(m, __shfl_xor_sync(0xffffffffu, m, o));
    float e0 = expf(a0 - m);
    float e1 = (j1 < CH) ? expf(a1 - m) : 0.f;

    float c0 = 0.f, c1 = 0.f;
#pragma unroll
    for (int kx = 0; kx < 4; kx++) {
        float th = sth[warp][kx];
        float zz = (a0 >= th ? e0 : 0.f) + ((j1 < CH && a1 >= th) ? e1 : 0.f);
#pragma unroll
        for (int o = 16; o; o >>= 1) zz += __shfl_xor_sync(0xffffffffu, zz, o);
        float f = wts[kx] / zz;
        if (a0 >= th) c0 += f;
        if (j1 < CH && a1 >= th) c1 += f;
    }
    coef[row * CH + j0] = e0 * c0;
    if (j1 < CH) coef[row * CH + j1] = e1 * c1;
}

// ------- cout = coef @ vc, packed i-pairs, broadcast shared loads -----------
__global__ __launch_bounds__(256) void cout_kernel(
    const float* __restrict__ coef, const float* __restrict__ dw,
    float* __restrict__ out)
{
    int bh = blockIdx.y; int b = bh >> 3, h = bh & 7;
    int p = blockIdx.x * 256 + threadIdx.x;
    __shared__ u64t scp[CH][CH / 2];
    const float* cf = coef + bh * CH * CH;
    for (int e = threadIdx.x; e < CH * (CH / 2); e += 256) {
        int j = e / (CH / 2), i2 = e % (CH / 2);
        scp[j][i2] = pack2(cf[(2 * i2) * CH + j], cf[(2 * i2 + 1) * CH + j]);
    }
    __syncthreads();
    const float* vb = dw + ((size_t)b * NQKV + 2 * NCH + h * CH) * P_PIX + p;
    u64t acc2[CH / 2];
#pragma unroll
    for (int i = 0; i < CH / 2; i++) acc2[i] = 0ull;
    for (int j = 0; j < CH; j++) {
        u64t vd = dup_f32(vb[(size_t)j * P_PIX]);
#pragma unroll
        for (int i = 0; i < CH / 2; i++) ffma2(acc2[i], vd, scp[j][i]);
    }
    float* ob = out + ((size_t)b * NCH + h * CH) * P_PIX + p;
#pragma unroll
    for (int i = 0; i < CH / 2; i++) {
        float lo, hi;
        asm("mov.b64 {%0, %1}, %2;" : "=f"(lo), "=f"(hi) : "l"(acc2[i]));
        ob[(size_t)(2 * i) * P_PIX]     = lo;
        ob[(size_t)(2 * i + 1) * P_PIX] = hi;
    }
}

// ---------------- fused spatial window attention (f32x2 math) ----------------
#define SQ_STR 50
#define SAT_STR 66
__global__ __launch_bounds__(256) void spatial_kernel(
    const float* __restrict__ dw, const float* __restrict__ temp,
    const float* __restrict__ w1p, const float* __restrict__ w2p,
    const float* __restrict__ w3p, const float* __restrict__ w4p,
    float* __restrict__ out)
{
    extern __shared__ float smemf[];
    float* sq  = smemf;
    float* sk2 = sq  + 64 * SQ_STR;
    float* svT = sk2 + 64 * SQ_STR;
    float* sat = svT + 48 * SAT_STR;
    float* nq  = sat + 64 * SAT_STR;
    float* nk  = nq  + 64;
    float* sth = nk  + 64;

    const int win = blockIdx.x;
    const int head = blockIdx.y;
    const int b = win >> 8, wy = (win >> 4) & 15, wx = win & 15;
    const int tid = threadIdx.x;

    const size_t base = ((size_t)b * NQKV + head * CH) * P_PIX + (size_t)(wy * 8) * 128 + wx * 8;

    for (int e = tid; e < NWIN * CH; e += 256) {
        int c = e >> 6, n = e & 63;
        int iy = n >> 3, ix = n & 7;
        size_t off = (size_t)c * P_PIX + iy * 128 + ix;
        sq [n * SQ_STR + c] = dw[base + off];
        sk2[n * SQ_STR + c] = dw[base + (size_t)NCH * P_PIX + off];
        svT[c * SAT_STR + n] = dw[base + (size_t)(2 * NCH) * P_PIX + off];
    }
    __syncthreads();

    if (tid < 128) {
        int n = tid & 63;
        const float* src = (tid < 64) ? sq : sk2;
        float s = 0.f;
#pragma unroll
        for (int c = 0; c < CH; c++) { float v = src[n * SQ_STR + c]; s = fmaf(v, v, s); }
        float nn = fmaxf(sqrtf(s), 1e-12f);
        if (tid < 64) nq[n] = nn; else nk[n] = nn;
    }
    __syncthreads();

    const float t = temp[wx & 7];
#pragma unroll
    for (int o = 0; o < 16; o++) {
        int e = tid + o * 256;
        int n = e >> 6, m = e & 63;
        const u64t* qp = reinterpret_cast<const u64t*>(&sq[n * SQ_STR]);
        const u64t* kp = reinterpret_cast<const u64t*>(&sk2[m * SQ_STR]);
        u64t s2 = 0ull;
#pragma unroll
        for (int c2 = 0; c2 < CH / 2; c2++) ffma2(s2, qp[c2], kp[c2]);
        sat[n * SAT_STR + m] = pair_sum(s2) / (nq[n] * nk[m]) * t;
    }
    __syncthreads();

    const int warp = tid >> 5, ln = tid & 31;
    const int KT[4] = {31, 41, 47, 50};
    float wts[4] = {w1p[0], w2p[0], w3p[0], w4p[0]};

    for (int rr = 0; rr < 8; rr++) {
        int n = warp * 8 + rr;
        float a0 = sat[n * SAT_STR + ln];
        float a1 = sat[n * SAT_STR + ln + 32];
        int r0 = 0, r1 = 0;
        for (int i2 = 0; i2 < NWIN; i2++) {
            float ai = sat[n * SAT_STR + i2];
            r0 += (ai > a0) || (ai == a0 && i2 < ln);
            r1 += (ai > a1) || (ai == a1 && i2 < ln + 32);
        }
#pragma unroll
        for (int kx = 0; kx < 4; kx++) {
            if (r0 == KT[kx]) sth[n * 4 + kx] = a0;
            if (r1 == KT[kx]) sth[n * 4 + kx] = a1;
        }
        __syncwarp();

        float m = fmaxf(a0, a1);
#pragma unroll
        for (int o = 16; o; o >>= 1) m = fmaxf(m, __shfl_xor_sync(0xffffffffu, m, o));
        float e0 = expf(a0 - m), e1 = expf(a1 - m);

        float c0 = 0.f, c1 = 0.f;
#pragma unroll
        for (int kx = 0; kx < 4; kx++) {
            float th = sth[n * 4 + kx];
            float zz = (a0 >= th ? e0 : 0.f) + (a1 >= th ? e1 : 0.f);
#pragma unroll
            for (int o = 16; o; o >>= 1) zz += __shfl_xor_sync(0xffffffffu, zz, o);
            float f = wts[kx] / zz;
            if (a0 >= th) c0 += f;
            if (a1 >= th) c1 += f;
        }
        __syncwarp();
        sat[n * SAT_STR + ln]      = e0 * c0;
        sat[n * SAT_STR + ln + 32] = e1 * c1;
        __syncwarp();
    }
    __syncthreads();

#pragma unroll
    for (int o = 0; o < 12; o++) {
        int e = tid + o * 256;
        int c = e >> 6, n = e & 63;
        const u64t* ap = reinterpret_cast<const u64t*>(&sat[n * SAT_STR]);
        const u64t* vp = reinterpret_cast<const u64t*>(&svT[c * SAT_STR]);
        u64t s2 = 0ull;
#pragma unroll
        for (int m2 = 0; m2 < NWIN / 2; m2++) ffma2(s2, ap[m2], vp[m2]);
        int p = wy * 1024 + wx * 64 + n;
        size_t oidx = ((size_t)b * NCH + head * CH + c) * P_PIX + p;
        out[oidx] += pair_sum(s2);
    }
}

// ---------------- host launcher ----------------
extern "C" void kernel_launch(void* const* d_in, const int* in_sizes, int n_in,
                              void* d_out, int out_size)
{
    const float* x      = (const float*)d_in[0];
    const float* w_qkv  = (const float*)d_in[1];
    const float* w_dw   = (const float*)d_in[2];
    const float* w_proj = (const float*)d_in[3];
    const float* temp   = (const float*)d_in[4];
    const float* a1     = (const float*)d_in[5];
    const float* a2     = (const float*)d_in[6];
    const float* a3     = (const float*)d_in[7];
    const float* a4     = (const float*)d_in[8];
    float* out = (float*)d_out;

    float *qkv, *dwb, *sum, *cnq, *cnk, *cpart, *ccoef;
    __nv_bfloat16 *xth, *xtl, *wqh, *wql, *wph, *wpl;
    cudaGetSymbolAddress((void**)&qkv,   g_qkv);
    cudaGetSymbolAddress((void**)&dwb,   g_dw);
    cudaGetSymbolAddress((void**)&sum,   g_sum);
    cudaGetSymbolAddress((void**)&cnq,   g_cnq);
    cudaGetSymbolAddress((void**)&cnk,   g_cnk);
    cudaGetSymbolAddress((void**)&cpart, g_cpart);
    cudaGetSymbolAddress((void**)&ccoef, g_ccoef);
    cudaGetSymbolAddress((void**)&xth,   g_xth);
    cudaGetSymbolAddress((void**)&xtl,   g_xtl);
    cudaGetSymbolAddress((void**)&wqh,   g_wqh);
    cudaGetSymbolAddress((void**)&wql,   g_wql);
    cudaGetSymbolAddress((void**)&wph,   g_wph);
    cudaGetSymbolAddress((void**)&wpl,   g_wpl);

    const int spatial_smem =
        (64 * SQ_STR * 2 + 48 * SAT_STR + 64 * SAT_STR + 64 + 64 + 64 * 4) * 4;
    const int gemm_smem = 4 * 128 * A_STR * 2;   // 73728 bytes
    cudaFuncSetAttribute(spatial_kernel, cudaFuncAttributeMaxDynamicSharedMemorySize, 65536);
    cudaFuncSetAttribute(hmma_gemm, cudaFuncAttributeMaxDynamicSharedMemorySize, gemm_smem);

    // 0) weight splits + X transpose/split
    convert_w<<<(NQKV * NCH + 255) / 256, 256>>>(w_qkv, wqh, wql, NQKV * NCH);
    convert_w<<<(NCH * NCH + 255) / 256, 256>>>(w_proj, wph, wpl, NCH * NCH);
    transpose_split<<<dim3(P_PIX / 32, GK / 32, 2), 256>>>(x, xth, xtl);
    // 1) qkv = 1x1 conv via split-bf16 HMMA (M=1152)
    hmma_gemm<<<dim3(P_PIX / 128, NQKV / 128, 2), 256, gemm_smem>>>(wqh, wql, xth, xtl, qkv, NQKV);
    // 2) depthwise 3x3
    dwconv_kernel<<<(2 * NQKV * P_PIX / 4) / 256, 256>>>(qkv, w_dw, dwb);
    // 3) channel-row norms
    chan_norms_kernel<<<2 * 2 * NCH, 256>>>(dwb, cnq, cnk);
    // 4) cattn split-K partials
    cattn_kernel<<<dim3(CSPLIT, 16), 256>>>(dwb, cpart);
    // 5) channel softmax coefficients
    chan_coef_kernel<<<96, 256>>>(cpart, cnq, cnk, temp, a1, a2, a3, a4, ccoef);
    // 6) cout = coef @ v
    cout_kernel<<<dim3(P_PIX / 256, 16), 256>>>(ccoef, dwb, sum);
    // 7) fused spatial window attention (adds into g_sum)
    spatial_kernel<<<dim3(512, HEADS), 256, spatial_smem>>>(dwb, temp, a1, a2, a3, a4, sum);
    // 8) proj: transpose/split g_sum, then HMMA GEMM (M=384) -> d_out
    transpose_split<<<dim3(P_PIX / 32, GK / 32, 2), 256>>>(sum, xth, xtl);
    hmma_gemm<<<dim3(P_PIX / 128, NCH / 128, 2), 256, gemm_smem>>>(wph, wpl, xth, xtl, out, NCH);
}

// round 7
// speedup vs baseline: 2.3584x; 1.1270x over previous
#include <cuda_runtime.h>
#include <cuda_bf16.h>
#include <math.h>
#include <cstdint>

#define P_PIX 16384   // 128*128
#define NCH   384
#define NQKV  1152
#define HEADS 8
#define CH    48      // per-head channels
#define NWIN  64      // tokens per 8x8 window
#define CSPLIT 32     // cattn K splits
#define GK    384     // GEMM K (both gemms)
#define BK    32      // K chunk (cp.async stage)
#define NKC   (GK / BK)   // 12 chunks
#define A_STR 40      // smem row stride (bf16), 80B: conflict-free ldmatrix
#define AS    (128 * A_STR)   // elems per array tile

typedef unsigned long long u64t;

__device__ __forceinline__ u64t dup_f32(float a) {
    u64t r; asm("mov.b64 %0, {%1, %1};" : "=l"(r) : "f"(a)); return r;
}
__device__ __forceinline__ void ffma2(u64t& acc, u64t a, u64t b) {
    asm("fma.rn.f32x2 %0, %1, %2, %0;" : "+l"(acc) : "l"(a), "l"(b));
}
__device__ __forceinline__ u64t pack2(float lo, float hi) {
    u64t r; asm("mov.b64 %0, {%1, %2};" : "=l"(r) : "f"(lo), "f"(hi)); return r;
}
__device__ __forceinline__ uint32_t smem_u32(const void* p) {
    uint32_t a;
    asm("{ .reg .u64 t; cvta.to.shared.u64 t, %1; cvt.u32.u64 %0, t; }" : "=r"(a) : "l"(p));
    return a;
}
__device__ __forceinline__ void ldsm_x4(uint32_t* r, uint32_t addr) {
    asm volatile("ldmatrix.sync.aligned.m8n8.x4.shared.b16 {%0,%1,%2,%3}, [%4];"
                 : "=r"(r[0]), "=r"(r[1]), "=r"(r[2]), "=r"(r[3]) : "r"(addr));
}
__device__ __forceinline__ void ldsm_x2(uint32_t* r, uint32_t addr) {
    asm volatile("ldmatrix.sync.aligned.m8n8.x2.shared.b16 {%0,%1}, [%2];"
                 : "=r"(r[0]), "=r"(r[1]) : "r"(addr));
}
__device__ __forceinline__ void mma_bf16(float* c, const uint32_t* a, const uint32_t* b) {
    asm volatile("mma.sync.aligned.m16n8k16.row.col.f32.bf16.bf16.f32 "
                 "{%0,%1,%2,%3}, {%4,%5,%6,%7}, {%8,%9}, {%0,%1,%2,%3};"
                 : "+f"(c[0]), "+f"(c[1]), "+f"(c[2]), "+f"(c[3])
                 : "r"(a[0]), "r"(a[1]), "r"(a[2]), "r"(a[3]), "r"(b[0]), "r"(b[1]));
}
__device__ __forceinline__ void cp_async16(uint32_t saddr, const void* g) {
    asm volatile("cp.async.cg.shared.global [%0], [%1], 16;" :: "r"(saddr), "l"(g));
}
#define CP_COMMIT() asm volatile("cp.async.commit_group;" ::: "memory")
#define CP_WAIT1()  asm volatile("cp.async.wait_group 1;" ::: "memory")
#define CP_WAIT0()  asm volatile("cp.async.wait_group 0;" ::: "memory")

// ---------------- scratch (device globals; no allocs allowed) ----------------
__device__ float g_qkv[2ll * NQKV * P_PIX];
__device__ float g_dw [2ll * NQKV * P_PIX];
__device__ float g_sum[2ll * NCH  * P_PIX];
__device__ float g_cnq[2 * NCH];
__device__ float g_cnk[2 * NCH];
__device__ float g_cpart[CSPLIT * 16 * CH * CH];
__device__ float g_ccoef[16 * CH * CH];
__device__ __nv_bfloat16 g_xth[2ll * P_PIX * GK];
__device__ __nv_bfloat16 g_xtl[2ll * P_PIX * GK];
__device__ __nv_bfloat16 g_wqh[NQKV * NCH];
__device__ __nv_bfloat16 g_wql[NQKV * NCH];
__device__ __nv_bfloat16 g_wph[NCH * NCH];
__device__ __nv_bfloat16 g_wpl[NCH * NCH];

// ---------------- weight split fp32 -> bf16 hi/lo ----------------
__global__ __launch_bounds__(256) void convert_w(
    const float* __restrict__ W, __nv_bfloat16* __restrict__ Wh,
    __nv_bfloat16* __restrict__ Wl, int n)
{
    int i = blockIdx.x * 256 + threadIdx.x;
    if (i >= n) return;
    float v = W[i];
    __nv_bfloat16 hi = __float2bfloat16(v);
    Wh[i] = hi;
    Wl[i] = __float2bfloat16(v - __bfloat162float(hi));
}

// ------- transpose+split: X fp32 [b][K=384][16384] -> T bf16 [b][16384][384] --
__global__ __launch_bounds__(256) void transpose_split(
    const float* __restrict__ X, __nv_bfloat16* __restrict__ Th,
    __nv_bfloat16* __restrict__ Tl)
{
    __shared__ float s[32][33];
    const int b  = blockIdx.z;
    const int p0 = blockIdx.x * 32;
    const int k0 = blockIdx.y * 32;
    const int tid = threadIdx.x;
    const int tx = tid & 31, ty = tid >> 5;
    const float* Xb = X + ((size_t)b * GK + k0) * P_PIX + p0;
#pragma unroll
    for (int i = 0; i < 4; i++)
        s[ty + 8 * i][tx] = Xb[(size_t)(ty + 8 * i) * P_PIX + tx];
    __syncthreads();
    const int row = tid >> 3;
    const int kk = (tid & 7) * 4;
    __nv_bfloat16 hv[4], lv[4];
#pragma unroll
    for (int j = 0; j < 4; j++) {
        float v = s[kk + j][row];
        hv[j] = __float2bfloat16(v);
        lv[j] = __float2bfloat16(v - __bfloat162float(hv[j]));
    }
    size_t ob = ((size_t)b * P_PIX + p0 + row) * GK + k0 + kk;
    *reinterpret_cast<__nv_bfloat162*>(&Th[ob])     = *reinterpret_cast<__nv_bfloat162*>(&hv[0]);
    *reinterpret_cast<__nv_bfloat162*>(&Th[ob + 2]) = *reinterpret_cast<__nv_bfloat162*>(&hv[2]);
    *reinterpret_cast<__nv_bfloat162*>(&Tl[ob])     = *reinterpret_cast<__nv_bfloat162*>(&lv[0]);
    *reinterpret_cast<__nv_bfloat162*>(&Tl[ob + 2]) = *reinterpret_cast<__nv_bfloat162*>(&lv[2]);
}

// ------------- split-bf16 HMMA GEMM, cp.async double-buffered ---------------
// A = W (hi/lo [m][k]); B = X^T (hi/lo [p][k]). CTA 128x128, warp 64x32.
__global__ __launch_bounds__(256, 2) void hmma_gemm(
    const __nv_bfloat16* __restrict__ Wh, const __nv_bfloat16* __restrict__ Wl,
    const __nv_bfloat16* __restrict__ Th, const __nv_bfloat16* __restrict__ Tl,
    float* __restrict__ Y, int M)
{
    extern __shared__ __nv_bfloat16 sm[];
    const uint32_t sm32 = smem_u32(sm);

    const int tid = threadIdx.x;
    const int wid = tid >> 5, lane = tid & 31;
    const int wr = wid >> 2;          // 0..1
    const int wc = wid & 3;           // 0..3
    const int b  = blockIdx.z;
    const int m0 = blockIdx.y * 128;
    const int p0 = blockIdx.x * 128;

    const __nv_bfloat16* gA[4];
    gA[0] = Wh + (size_t)m0 * GK;
    gA[1] = Wl + (size_t)m0 * GK;
    gA[2] = Th + ((size_t)b * P_PIX + p0) * GK;
    gA[3] = Tl + ((size_t)b * P_PIX + p0) * GK;

    float acc[4][4][4];
#pragma unroll
    for (int i = 0; i < 4; i++)
#pragma unroll
        for (int j = 0; j < 4; j++)
#pragma unroll
            for (int r = 0; r < 4; r++) acc[i][j][r] = 0.f;

    // issue one stage: 4 arrays x 128 rows x 32 cols; 512 x16B per array
    auto issue = [&](int chunk, int buf) {
        const int kb = chunk * BK;
        const uint32_t bufb = sm32 + (uint32_t)buf * 4 * AS * 2;
#pragma unroll
        for (int i = 0; i < 2; i++) {
            int idx = tid + i * 256;             // 0..511
            int row = idx >> 2, c8 = (idx & 3) * 8;
            size_t go = (size_t)row * GK + kb + c8;
            uint32_t so = bufb + (uint32_t)(row * A_STR + c8) * 2;
#pragma unroll
            for (int a = 0; a < 4; a++)
                cp_async16(so + (uint32_t)a * AS * 2, gA[a] + go);
        }
        CP_COMMIT();
    };

    issue(0, 0);
    issue(1, 1);

    for (int c = 0; c < NKC; c++) {
        if (c + 1 < NKC) CP_WAIT1(); else CP_WAIT0();
        __syncthreads();
        const uint32_t bufb = sm32 + (uint32_t)(c & 1) * 4 * AS * 2;
        const uint32_t sAh32 = bufb;
        const uint32_t sAl32 = bufb + AS * 2;
        const uint32_t sBh32 = bufb + 2 * AS * 2;
        const uint32_t sBl32 = bufb + 3 * AS * 2;

#pragma unroll
        for (int ks = 0; ks < BK / 16; ks++) {
            const int k0 = ks * 16;
            uint32_t bH[4][2], bL[4][2];
            {
                int nrow = wc * 32 + (lane & 7);
                int ncol = k0 + ((lane >> 3) & 1) * 8;
#pragma unroll
                for (int nt = 0; nt < 4; nt++) {
                    uint32_t off = (uint32_t)((nrow + nt * 8) * A_STR + ncol) * 2;
                    ldsm_x2(bH[nt], sBh32 + off);
                    ldsm_x2(bL[nt], sBl32 + off);
                }
            }
            {
                int arow = wr * 64 + (lane & 15);
                int acol = k0 + (lane >> 4) * 8;
                uint32_t aH[4][4];
#pragma unroll
                for (int mt = 0; mt < 4; mt++)
                    ldsm_x4(aH[mt], sAh32 + (uint32_t)((arow + mt * 16) * A_STR + acol) * 2);
#pragma unroll
                for (int mt = 0; mt < 4; mt++)
#pragma unroll
                    for (int nt = 0; nt < 4; nt++) {
                        mma_bf16(acc[mt][nt], aH[mt], bH[nt]);
                        mma_bf16(acc[mt][nt], aH[mt], bL[nt]);
                    }
                uint32_t aL[4][4];
#pragma unroll
                for (int mt = 0; mt < 4; mt++)
                    ldsm_x4(aL[mt], sAl32 + (uint32_t)((arow + mt * 16) * A_STR + acol) * 2);
#pragma unroll
                for (int mt = 0; mt < 4; mt++)
#pragma unroll
                    for (int nt = 0; nt < 4; nt++)
                        mma_bf16(acc[mt][nt], aL[mt], bH[nt]);
            }
        }
        __syncthreads();
        if (c + 2 < NKC) issue(c + 2, c & 1);
    }

    // epilogue
    const int tq = lane >> 2;
    const int tr4 = lane & 3;
#pragma unroll
    for (int mt = 0; mt < 4; mt++) {
#pragma unroll
        for (int nt = 0; nt < 4; nt++) {
            int m  = m0 + wr * 64 + mt * 16 + tq;
            int p  = p0 + wc * 32 + nt * 8 + tr4 * 2;
            float* y0 = &Y[((size_t)b * M + m) * P_PIX + p];
            *reinterpret_cast<float2*>(y0) = make_float2(acc[mt][nt][0], acc[mt][nt][1]);
            float* y1 = &Y[((size_t)b * M + m + 8) * P_PIX + p];
            *reinterpret_cast<float2*>(y1) = make_float2(acc[mt][nt][2], acc[mt][nt][3]);
        }
    }
}

// ---------------- depthwise 3x3, pad 1, 4 pixels/thread ----------------
__global__ __launch_bounds__(256) void dwconv_kernel(
    const float* __restrict__ in, const float* __restrict__ Wd, float* __restrict__ out)
{
    int gid = blockIdx.x * 256 + threadIdx.x;
    int grp = gid & 4095;
    int bc  = gid >> 12;
    int ch  = bc % NQKV;
    int x0 = (grp & 31) * 4, y = grp >> 5;
    const float* ip = in + (size_t)bc * P_PIX;
    const float* w  = Wd + ch * 9;
    float o0 = 0.f, o1 = 0.f, o2 = 0.f, o3 = 0.f;
#pragma unroll
    for (int dy = -1; dy <= 1; dy++) {
        int yy = y + dy;
        if ((unsigned)yy >= 128u) continue;
        const float* rp = ip + yy * 128;
        float v[6];
#pragma unroll
        for (int t = 0; t < 6; t++) {
            int xx = x0 - 1 + t;
            v[t] = ((unsigned)xx < 128u) ? rp[xx] : 0.f;
        }
#pragma unroll
        for (int dx = 0; dx < 3; dx++) {
            float wv = w[(dy + 1) * 3 + dx];
            o0 = fmaf(wv, v[dx + 0], o0);
            o1 = fmaf(wv, v[dx + 1], o1);
            o2 = fmaf(wv, v[dx + 2], o2);
            o3 = fmaf(wv, v[dx + 3], o3);
        }
    }
    *reinterpret_cast<float4*>(&out[(size_t)bc * P_PIX + y * 128 + x0]) =
        make_float4(o0, o1, o2, o3);
}

// ---------------- per-channel-row L2 norms over 16384 (q and k) -------------
__global__ __launch_bounds__(256) void chan_norms_kernel(
    const float* __restrict__ dw, float* __restrict__ nq, float* __restrict__ nk)
{
    int row = blockIdx.x;
    int b = row / 768;
    int r = row % 768;
    const float* p = dw + ((size_t)b * NQKV + r) * P_PIX;
    float s = 0.f;
    for (int i = threadIdx.x * 4; i < P_PIX; i += 1024) {
        float4 v = *reinterpret_cast<const float4*>(&p[i]);
        s = fmaf(v.x, v.x, s); s = fmaf(v.y, v.y, s);
        s = fmaf(v.z, v.z, s); s = fmaf(v.w, v.w, s);
    }
    __shared__ float red[256];
    red[threadIdx.x] = s; __syncthreads();
    for (int st = 128; st > 0; st >>= 1) {
        if (threadIdx.x < st) red[threadIdx.x] += red[threadIdx.x + st];
        __syncthreads();
    }
    if (threadIdx.x == 0) {
        float n = fmaxf(sqrtf(red[0]), 1e-12f);
        if (r < NCH) nq[b * NCH + r] = n; else nk[b * NCH + (r - NCH)] = n;
    }
}

// ------ cattn raw dots, split-K partials, 3x3 register tiling ---------------
__global__ __launch_bounds__(256) void cattn_kernel(
    const float* __restrict__ dw, float* __restrict__ part)
{
    const int bh = blockIdx.y;
    const int b = bh >> 3, h = bh & 7;
    const int kbase = blockIdx.x * (P_PIX / CSPLIT);
    const float* qb = dw + ((size_t)b * NQKV + h * CH) * P_PIX;
    const float* kb = dw + ((size_t)b * NQKV + NCH + h * CH) * P_PIX;

    __shared__ float sq[CH][65];
    __shared__ float sk[CH][65];

    const int tid = threadIdx.x;
    const int ti = tid >> 4, tj = tid & 15;
    const int i0 = ti * 3, j0 = tj * 3;

    float acc[3][3];
#pragma unroll
    for (int r = 0; r < 3; r++)
#pragma unroll
        for (int c = 0; c < 3; c++) acc[r][c] = 0.f;

    for (int kc = 0; kc < P_PIX / CSPLIT; kc += 64) {
        const int kpos = kbase + kc;
        for (int e = tid; e < CH * 16; e += 256) {
            int r = e >> 4, c4 = (e & 15) * 4;
            float4 vq = *reinterpret_cast<const float4*>(&qb[(size_t)r * P_PIX + kpos + c4]);
            float4 vk = *reinterpret_cast<const float4*>(&kb[(size_t)r * P_PIX + kpos + c4]);
            sq[r][c4] = vq.x; sq[r][c4+1] = vq.y; sq[r][c4+2] = vq.z; sq[r][c4+3] = vq.w;
            sk[r][c4] = vk.x; sk[r][c4+1] = vk.y; sk[r][c4+2] = vk.z; sk[r][c4+3] = vk.w;
        }
        __syncthreads();
#pragma unroll 8
        for (int kk = 0; kk < 64; kk++) {
            float a0 = sq[i0][kk], a1 = sq[i0+1][kk], a2 = sq[i0+2][kk];
            float b0 = sk[j0][kk], b1 = sk[j0+1][kk], b2 = sk[j0+2][kk];
            acc[0][0] = fmaf(a0, b0, acc[0][0]);
            acc[0][1] = fmaf(a0, b1, acc[0][1]);
            acc[0][2] = fmaf(a0, b2, acc[0][2]);
            acc[1][0] = fmaf(a1, b0, acc[1][0]);
            acc[1][1] = fmaf(a1, b1, acc[1][1]);
            acc[1][2] = fmaf(a1, b2, acc[1][2]);
            acc[2][0] = fmaf(a2, b0, acc[2][0]);
            acc[2][1] = fmaf(a2, b1, acc[2][1]);
            acc[2][2] = fmaf(a2, b2, acc[2][2]);
        }
        __syncthreads();
    }
    float* pr = &part[((size_t)blockIdx.x * 16 + bh) * (CH * CH)];
#pragma unroll
    for (int r = 0; r < 3; r++)
#pragma unroll
        for (int c = 0; c < 3; c++)
            pr[(i0 + r) * CH + (j0 + c)] = acc[r][c];
}

// ------- channel branch: combined top-k softmax coefficients ----------------
__global__ __launch_bounds__(256) void chan_coef_kernel(
    const float* __restrict__ part, const float* __restrict__ nq,
    const float* __restrict__ nk, const float* __restrict__ temp,
    const float* __restrict__ w1p, const float* __restrict__ w2p,
    const float* __restrict__ w3p, const float* __restrict__ w4p,
    float* __restrict__ coef)
{
    const int warp = threadIdx.x >> 5, ln = threadIdx.x & 31;
    const int row = blockIdx.x * 8 + warp;
    const int bh = row / CH, i = row % CH;
    const int b = bh >> 3, h = bh & 7;
    const float t = temp[h];
    const float inq = 1.f / nq[b * NCH + h * CH + i];
    const int KT[4] = {23, 31, 35, 37};
    float wts[4] = {w1p[0], w2p[0], w3p[0], w4p[0]};

    __shared__ float sa[8][CH];
    __shared__ float sth[8][4];

    int j0 = ln, j1 = ln + 32;
    float d0 = 0.f, d1 = 0.f;
    for (int s = 0; s < CSPLIT; s++) {
        const float* pr = part + ((size_t)s * 16 + bh) * (CH * CH) + i * CH;
        d0 += pr[j0];
        if (j1 < CH) d1 += pr[j1];
    }
    float a0 = d0 * inq / nk[b * NCH + h * CH + j0] * t;
    float a1 = (j1 < CH) ? d1 * inq / nk[b * NCH + h * CH + j1] * t : -INFINITY;
    sa[warp][j0] = a0;
    if (j1 < CH) sa[warp][j1] = a1;
    __syncwarp();

    int r0 = 0, r1 = 0;
    for (int q = 0; q < CH; q++) {
        float aq = sa[warp][q];
        r0 += (aq > a0) || (aq == a0 && q < j0);
        if (j1 < CH) r1 += (aq > a1) || (aq == a1 && q < j1);
    }
#pragma unroll
    for (int kx = 0; kx < 4; kx++) {
        if (r0 == KT[kx]) sth[warp][kx] = a0;
        if (j1 < CH && r1 == KT[kx]) sth[warp][kx] = a1;
    }
    __syncwarp();

    float m = fmaxf(a0, a1);
#pragma unroll
    for (int o = 16; o; o >>= 1) m = fmaxf(m, __shfl_xor_sync(0xffffffffu, m, o));
    float e0 = expf(a0 - m);
    float e1 = (j1 < CH) ? expf(a1 - m) : 0.f;

    float c0 = 0.f, c1 = 0.f;
#pragma unroll
    for (int kx = 0; kx < 4; kx++) {
        float th = sth[warp][kx];
        float zz = (a0 >= th ? e0 : 0.f) + ((j1 < CH && a1 >= th) ? e1 : 0.f);
#pragma unroll
        for (int o = 16; o; o >>= 1) zz += __shfl_xor_sync(0xffffffffu, zz, o);
        float f = wts[kx] / zz;
        if (a0 >= th) c0 += f;
        if (j1 < CH && a1 >= th) c1 += f;
    }
    coef[row * CH + j0] = e0 * c0;
    if (j1 < CH) coef[row * CH + j1] = e1 * c1;
}

// ------- cout = coef @ vc, packed i-pairs, broadcast shared loads -----------
__global__ __launch_bounds__(256) void cout_kernel(
    const float* __restrict__ coef, const float* __restrict__ dw,
    float* __restrict__ out)
{
    int bh = blockIdx.y; int b = bh >> 3, h = bh & 7;
    int p = blockIdx.x * 256 + threadIdx.x;
    __shared__ u64t scp[CH][CH / 2];
    const float* cf = coef + bh * CH * CH;
    for (int e = threadIdx.x; e < CH * (CH / 2); e += 256) {
        int j = e / (CH / 2), i2 = e % (CH / 2);
        scp[j][i2] = pack2(cf[(2 * i2) * CH + j], cf[(2 * i2 + 1) * CH + j]);
    }
    __syncthreads();
    const float* vb = dw + ((size_t)b * NQKV + 2 * NCH + h * CH) * P_PIX + p;
    u64t acc2[CH / 2];
#pragma unroll
    for (int i = 0; i < CH / 2; i++) acc2[i] = 0ull;
    for (int j = 0; j < CH; j++) {
        u64t vd = dup_f32(vb[(size_t)j * P_PIX]);
#pragma unroll
        for (int i = 0; i < CH / 2; i++) ffma2(acc2[i], vd, scp[j][i]);
    }
    float* ob = out + ((size_t)b * NCH + h * CH) * P_PIX + p;
#pragma unroll
    for (int i = 0; i < CH / 2; i++) {
        float lo, hi;
        asm("mov.b64 {%0, %1}, %2;" : "=f"(lo), "=f"(hi) : "l"(acc2[i]));
        ob[(size_t)(2 * i) * P_PIX]     = lo;
        ob[(size_t)(2 * i + 1) * P_PIX] = hi;
    }
}

// ------------- fused spatial window attention, register-tiled ----------------
#define SQ_STR 50
#define SAT_STR 66
__global__ __launch_bounds__(256) void spatial_kernel(
    const float* __restrict__ dw, const float* __restrict__ temp,
    const float* __restrict__ w1p, const float* __restrict__ w2p,
    const float* __restrict__ w3p, const float* __restrict__ w4p,
    float* __restrict__ out)
{
    extern __shared__ float smemf[];
    float* sq  = smemf;                      // 64*50 (later reused as obuf 48*66)
    float* sk2 = sq  + 64 * SQ_STR;          // 64*50
    float* svT = sk2 + 64 * SQ_STR;          // 48*66
    float* sat = svT + 48 * SAT_STR;         // 64*66
    float* nq  = sat + 64 * SAT_STR;         // 64
    float* nk  = nq  + 64;                   // 64
    float* sth = nk  + 64;                   // 64*4

    const int win = blockIdx.x;
    const int head = blockIdx.y;
    const int b = win >> 8, wy = (win >> 4) & 15, wx = win & 15;
    const int tid = threadIdx.x;
    const int ti = tid >> 4, tj = tid & 15;

    const size_t base = ((size_t)b * NQKV + head * CH) * P_PIX + (size_t)(wy * 8) * 128 + wx * 8;

    for (int e = tid; e < NWIN * CH; e += 256) {
        int c = e >> 6, n = e & 63;
        int iy = n >> 3, ix = n & 7;
        size_t off = (size_t)c * P_PIX + iy * 128 + ix;
        sq [n * SQ_STR + c] = dw[base + off];
        sk2[n * SQ_STR + c] = dw[base + (size_t)NCH * P_PIX + off];
        svT[c * SAT_STR + n] = dw[base + (size_t)(2 * NCH) * P_PIX + off];
    }
    __syncthreads();

    if (tid < 128) {
        int n = tid & 63;
        const float* src = (tid < 64) ? sq : sk2;
        float s = 0.f;
#pragma unroll
        for (int c = 0; c < CH; c++) { float v = src[n * SQ_STR + c]; s = fmaf(v, v, s); }
        float nn = fmaxf(sqrtf(s), 1e-12f);
        if (tid < 64) nq[n] = nn; else nk[n] = nn;
    }
    __syncthreads();

    const float t = temp[wx & 7];
    // QK^T: 4x4 tile per thread, interleaved: n = ti+16i, m = tj+16j
    {
        float accq[4][4];
#pragma unroll
        for (int i = 0; i < 4; i++)
#pragma unroll
            for (int j = 0; j < 4; j++) accq[i][j] = 0.f;
        for (int c = 0; c < CH; c++) {
            float qv[4], kv[4];
#pragma unroll
            for (int i = 0; i < 4; i++) qv[i] = sq[(ti + 16 * i) * SQ_STR + c];
#pragma unroll
            for (int j = 0; j < 4; j++) kv[j] = sk2[(tj + 16 * j) * SQ_STR + c];
#pragma unroll
            for (int i = 0; i < 4; i++)
#pragma unroll
                for (int j = 0; j < 4; j++)
                    accq[i][j] = fmaf(qv[i], kv[j], accq[i][j]);
        }
        float qn[4], kn[4];
#pragma unroll
        for (int i = 0; i < 4; i++) qn[i] = nq[ti + 16 * i];
#pragma unroll
        for (int j = 0; j < 4; j++) kn[j] = nk[tj + 16 * j];
#pragma unroll
        for (int i = 0; i < 4; i++)
#pragma unroll
            for (int j = 0; j < 4; j++)
                sat[(ti + 16 * i) * SAT_STR + tj + 16 * j] = accq[i][j] / (qn[i] * kn[j]) * t;
    }
    __syncthreads();

    const int warp = tid >> 5, ln = tid & 31;
    const int KT[4] = {31, 41, 47, 50};
    float wts[4] = {w1p[0], w2p[0], w3p[0], w4p[0]};

    for (int rr = 0; rr < 8; rr++) {
        int n = warp * 8 + rr;
        float a0 = sat[n * SAT_STR + ln];
        float a1 = sat[n * SAT_STR + ln + 32];
        int r0 = 0, r1 = 0;
        for (int i2 = 0; i2 < NWIN; i2++) {
            float ai = sat[n * SAT_STR + i2];
            r0 += (ai > a0) || (ai == a0 && i2 < ln);
            r1 += (ai > a1) || (ai == a1 && i2 < ln + 32);
        }
#pragma unroll
        for (int kx = 0; kx < 4; kx++) {
            if (r0 == KT[kx]) sth[n * 4 + kx] = a0;
            if (r1 == KT[kx]) sth[n * 4 + kx] = a1;
        }
        __syncwarp();

        float m = fmaxf(a0, a1);
#pragma unroll
        for (int o = 16; o; o >>= 1) m = fmaxf(m, __shfl_xor_sync(0xffffffffu, m, o));
        float e0 = expf(a0 - m), e1 = expf(a1 - m);

        float c0 = 0.f, c1 = 0.f;
#pragma unroll
        for (int kx = 0; kx < 4; kx++) {
            float th = sth[n * 4 + kx];
            float zz = (a0 >= th ? e0 : 0.f) + (a1 >= th ? e1 : 0.f);
#pragma unroll
            for (int o = 16; o; o >>= 1) zz += __shfl_xor_sync(0xffffffffu, zz, o);
            float f = wts[kx] / zz;
            if (a0 >= th) c0 += f;
            if (a1 >= th) c1 += f;
        }
        __syncwarp();
        sat[n * SAT_STR + ln]      = e0 * c0;
        sat[n * SAT_STR + ln + 32] = e1 * c1;
        __syncwarp();
    }
    __syncthreads();

    // A*V: 3x4 tile per thread: c = tj+16i, n = ti+16j; stage in obuf (= sq)
    {
        float acca[3][4];
#pragma unroll
        for (int i = 0; i < 3; i++)
#pragma unroll
            for (int j = 0; j < 4; j++) acca[i][j] = 0.f;
        for (int m = 0; m < NWIN; m++) {
            float av[4], vv[3];
#pragma unroll
            for (int j = 0; j < 4; j++) av[j] = sat[(ti + 16 * j) * SAT_STR + m];
#pragma unroll
            for (int i = 0; i < 3; i++) vv[i] = svT[(tj + 16 * i) * SAT_STR + m];
#pragma unroll
            for (int i = 0; i < 3; i++)
#pragma unroll
                for (int j = 0; j < 4; j++)
                    acca[i][j] = fmaf(av[j], vv[i], acca[i][j]);
        }
        float* obuf = sq;   // sq dead after QK^T
#pragma unroll
        for (int i = 0; i < 3; i++)
#pragma unroll
            for (int j = 0; j < 4; j++)
                obuf[(tj + 16 * i) * SAT_STR + ti + 16 * j] = acca[i][j];
    }
    __syncthreads();

    // coalesced global adds: p = wy*1024 + wx*64 + n
    {
        const float* obuf = sq;
#pragma unroll
        for (int o = 0; o < 12; o++) {
            int e = tid + o * 256;
            int c = e >> 6, n = e & 63;
            int p = wy * 1024 + wx * 64 + n;
            size_t oidx = ((size_t)b * NCH + head * CH + c) * P_PIX + p;
            out[oidx] += obuf[c * SAT_STR + n];
        }
    }
}

// ---------------- host launcher ----------------
extern "C" void kernel_launch(void* const* d_in, const int* in_sizes, int n_in,
                              void* d_out, int out_size)
{
    const float* x      = (const float*)d_in[0];
    const float* w_qkv  = (const float*)d_in[1];
    const float* w_dw   = (const float*)d_in[2];
    const float* w_proj = (const float*)d_in[3];
    const float* temp   = (const float*)d_in[4];
    const float* a1     = (const float*)d_in[5];
    const float* a2     = (const float*)d_in[6];
    const float* a3     = (const float*)d_in[7];
    const float* a4     = (const float*)d_in[8];
    float* out = (float*)d_out;

    float *qkv, *dwb, *sum, *cnq, *cnk, *cpart, *ccoef;
    __nv_bfloat16 *xth, *xtl, *wqh, *wql, *wph, *wpl;
    cudaGetSymbolAddress((void**)&qkv,   g_qkv);
    cudaGetSymbolAddress((void**)&dwb,   g_dw);
    cudaGetSymbolAddress((void**)&sum,   g_sum);
    cudaGetSymbolAddress((void**)&cnq,   g_cnq);
    cudaGetSymbolAddress((void**)&cnk,   g_cnk);
    cudaGetSymbolAddress((void**)&cpart, g_cpart);
    cudaGetSymbolAddress((void**)&ccoef, g_ccoef);
    cudaGetSymbolAddress((void**)&xth,   g_xth);
    cudaGetSymbolAddress((void**)&xtl,   g_xtl);
    cudaGetSymbolAddress((void**)&wqh,   g_wqh);
    cudaGetSymbolAddress((void**)&wql,   g_wql);
    cudaGetSymbolAddress((void**)&wph,   g_wph);
    cudaGetSymbolAddress((void**)&wpl,   g_wpl);

    const int spatial_smem =
        (64 * SQ_STR * 2 + 48 * SAT_STR + 64 * SAT_STR + 64 + 64 + 64 * 4) * 4;
    const int gemm_smem = 2 * 4 * AS * 2;   // 2 stages x 4 arrays x 128x40 bf16 = 81920 B
    cudaFuncSetAttribute(spatial_kernel, cudaFuncAttributeMaxDynamicSharedMemorySize, 65536);
    cudaFuncSetAttribute(hmma_gemm, cudaFuncAttributeMaxDynamicSharedMemorySize, gemm_smem);

    // 0) weight splits + X transpose/split
    convert_w<<<(NQKV * NCH + 255) / 256, 256>>>(w_qkv, wqh, wql, NQKV * NCH);
    convert_w<<<(NCH * NCH + 255) / 256, 256>>>(w_proj, wph, wpl, NCH * NCH);
    transpose_split<<<dim3(P_PIX / 32, GK / 32, 2), 256>>>(x, xth, xtl);
    // 1) qkv = 1x1 conv via split-bf16 HMMA (M=1152)
    hmma_gemm<<<dim3(P_PIX / 128, NQKV / 128, 2), 256, gemm_smem>>>(wqh, wql, xth, xtl, qkv, NQKV);
    // 2) depthwise 3x3
    dwconv_kernel<<<(2 * NQKV * P_PIX / 4) / 256, 256>>>(qkv, w_dw, dwb);
    // 3) channel-row norms
    chan_norms_kernel<<<2 * 2 * NCH, 256>>>(dwb, cnq, cnk);
    // 4) cattn split-K partials
    cattn_kernel<<<dim3(CSPLIT, 16), 256>>>(dwb, cpart);
    // 5) channel softmax coefficients
    chan_coef_kernel<<<96, 256>>>(cpart, cnq, cnk, temp, a1, a2, a3, a4, ccoef);
    // 6) cout = coef @ v
    cout_kernel<<<dim3(P_PIX / 256, 16), 256>>>(ccoef, dwb, sum);
    // 7) fused spatial window attention (adds into g_sum)
    spatial_kernel<<<dim3(512, HEADS), 256, spatial_smem>>>(dwb, temp, a1, a2, a3, a4, sum);
    // 8) proj: transpose/split g_sum, then HMMA GEMM (M=384) -> d_out
    transpose_split<<<dim3(P_PIX / 32, GK / 32, 2), 256>>>(sum, xth, xtl);
    hmma_gemm<<<dim3(P_PIX / 128, NCH / 128, 2), 256, gemm_smem>>>(wph, wpl, xth, xtl, out, NCH);
}

// round 9
// speedup vs baseline: 2.3996x; 1.0175x over previous
#include <cuda_runtime.h>
#include <cuda_bf16.h>
#include <math.h>
#include <cstdint>

#define P_PIX 16384   // 128*128
#define NCH   384
#define NQKV  1152
#define HEADS 8
#define CH    48      // per-head channels
#define NWIN  64      // tokens per 8x8 window
#define CSPLIT 32     // cattn K splits
#define GK    384     // GEMM K (both gemms)
#define BK    32      // K chunk (cp.async stage)
#define NKC   (GK / BK)   // 12 chunks
#define A_STR 40      // smem row stride (bf16), 80B: conflict-free ldmatrix
#define AS    (128 * A_STR)   // elems per array tile

typedef unsigned long long u64t;

__device__ __forceinline__ u64t dup_f32(float a) {
    u64t r; asm("mov.b64 %0, {%1, %1};" : "=l"(r) : "f"(a)); return r;
}
__device__ __forceinline__ void ffma2(u64t& acc, u64t a, u64t b) {
    asm("fma.rn.f32x2 %0, %1, %2, %0;" : "+l"(acc) : "l"(a), "l"(b));
}
__device__ __forceinline__ u64t pack2(float lo, float hi) {
    u64t r; asm("mov.b64 %0, {%1, %2};" : "=l"(r) : "f"(lo), "f"(hi)); return r;
}
__device__ __forceinline__ uint32_t smem_u32(const void* p) {
    uint32_t a;
    asm("{ .reg .u64 t; cvta.to.shared.u64 t, %1; cvt.u32.u64 %0, t; }" : "=r"(a) : "l"(p));
    return a;
}
__device__ __forceinline__ void ldsm_x4(uint32_t* r, uint32_t addr) {
    asm volatile("ldmatrix.sync.aligned.m8n8.x4.shared.b16 {%0,%1,%2,%3}, [%4];"
                 : "=r"(r[0]), "=r"(r[1]), "=r"(r[2]), "=r"(r[3]) : "r"(addr));
}
__device__ __forceinline__ void ldsm_x2(uint32_t* r, uint32_t addr) {
    asm volatile("ldmatrix.sync.aligned.m8n8.x2.shared.b16 {%0,%1}, [%2];"
                 : "=r"(r[0]), "=r"(r[1]) : "r"(addr));
}
__device__ __forceinline__ void mma_bf16(float* c, const uint32_t* a, const uint32_t* b) {
    asm volatile("mma.sync.aligned.m16n8k16.row.col.f32.bf16.bf16.f32 "
                 "{%0,%1,%2,%3}, {%4,%5,%6,%7}, {%8,%9}, {%0,%1,%2,%3};"
                 : "+f"(c[0]), "+f"(c[1]), "+f"(c[2]), "+f"(c[3])
                 : "r"(a[0]), "r"(a[1]), "r"(a[2]), "r"(a[3]), "r"(b[0]), "r"(b[1]));
}
__device__ __forceinline__ void cp_async16(uint32_t saddr, const void* g) {
    asm volatile("cp.async.cg.shared.global [%0], [%1], 16;" :: "r"(saddr), "l"(g));
}
#define CP_COMMIT() asm volatile("cp.async.commit_group;" ::: "memory")
#define CP_WAIT1()  asm volatile("cp.async.wait_group 1;" ::: "memory")
#define CP_WAIT0()  asm volatile("cp.async.wait_group 0;" ::: "memory")

// ---------------- scratch (device globals; no allocs allowed) ----------------
__device__ float g_qkv[2ll * NQKV * P_PIX];
__device__ float g_dw [2ll * NQKV * P_PIX];
__device__ float g_sum[2ll * NCH  * P_PIX];
__device__ float g_cpart[CSPLIT * 16 * CH * CH];
__device__ float g_cnp[CSPLIT * 16 * 96];      // per-split row sum-of-squares (48 q + 48 k)
__device__ float g_ccoef[16 * CH * CH];
__device__ __nv_bfloat16 g_xth[2ll * P_PIX * GK];
__device__ __nv_bfloat16 g_xtl[2ll * P_PIX * GK];
__device__ __nv_bfloat16 g_wqh[NQKV * NCH];
__device__ __nv_bfloat16 g_wql[NQKV * NCH];
__device__ __nv_bfloat16 g_wph[NCH * NCH];
__device__ __nv_bfloat16 g_wpl[NCH * NCH];

// ---------------- weight split fp32 -> bf16 hi/lo ----------------
__global__ __launch_bounds__(256) void convert_w(
    const float* __restrict__ W, __nv_bfloat16* __restrict__ Wh,
    __nv_bfloat16* __restrict__ Wl, int n)
{
    int i = blockIdx.x * 256 + threadIdx.x;
    if (i >= n) return;
    float v = W[i];
    __nv_bfloat16 hi = __float2bfloat16(v);
    Wh[i] = hi;
    Wl[i] = __float2bfloat16(v - __bfloat162float(hi));
}

// ------- transpose+split: X fp32 [b][K=384][16384] -> T bf16 [b][16384][384] --
__global__ __launch_bounds__(256) void transpose_split(
    const float* __restrict__ X, __nv_bfloat16* __restrict__ Th,
    __nv_bfloat16* __restrict__ Tl)
{
    __shared__ float s[32][33];
    const int b  = blockIdx.z;
    const int p0 = blockIdx.x * 32;
    const int k0 = blockIdx.y * 32;
    const int tid = threadIdx.x;
    const int tx = tid & 31, ty = tid >> 5;
    const float* Xb = X + ((size_t)b * GK + k0) * P_PIX + p0;
#pragma unroll
    for (int i = 0; i < 4; i++)
        s[ty + 8 * i][tx] = Xb[(size_t)(ty + 8 * i) * P_PIX + tx];
    __syncthreads();
    const int row = tid >> 3;
    const int kk = (tid & 7) * 4;
    __nv_bfloat16 hv[4], lv[4];
#pragma unroll
    for (int j = 0; j < 4; j++) {
        float v = s[kk + j][row];
        hv[j] = __float2bfloat16(v);
        lv[j] = __float2bfloat16(v - __bfloat162float(hv[j]));
    }
    size_t ob = ((size_t)b * P_PIX + p0 + row) * GK + k0 + kk;
    *reinterpret_cast<__nv_bfloat162*>(&Th[ob])     = *reinterpret_cast<__nv_bfloat162*>(&hv[0]);
    *reinterpret_cast<__nv_bfloat162*>(&Th[ob + 2]) = *reinterpret_cast<__nv_bfloat162*>(&hv[2]);
    *reinterpret_cast<__nv_bfloat162*>(&Tl[ob])     = *reinterpret_cast<__nv_bfloat162*>(&lv[0]);
    *reinterpret_cast<__nv_bfloat162*>(&Tl[ob + 2]) = *reinterpret_cast<__nv_bfloat162*>(&lv[2]);
}

// ------------- split-bf16 HMMA GEMM, cp.async double-buffered ---------------
// A = W (hi/lo [m][k]); B = X^T (hi/lo [p][k]). CTA 128x128, warp 64x32.
// 3-pass MMA schedule: 16 independent accumulator chains per pass.
__global__ __launch_bounds__(256, 2) void hmma_gemm(
    const __nv_bfloat16* __restrict__ Wh, const __nv_bfloat16* __restrict__ Wl,
    const __nv_bfloat16* __restrict__ Th, const __nv_bfloat16* __restrict__ Tl,
    float* __restrict__ Y, int M)
{
    extern __shared__ __nv_bfloat16 sm[];
    const uint32_t sm32 = smem_u32(sm);

    const int tid = threadIdx.x;
    const int wid = tid >> 5, lane = tid & 31;
    const int wr = wid >> 2;          // 0..1
    const int wc = wid & 3;           // 0..3
    const int b  = blockIdx.z;
    const int m0 = blockIdx.y * 128;
    const int p0 = blockIdx.x * 128;

    const __nv_bfloat16* gA[4];
    gA[0] = Wh + (size_t)m0 * GK;
    gA[1] = Wl + (size_t)m0 * GK;
    gA[2] = Th + ((size_t)b * P_PIX + p0) * GK;
    gA[3] = Tl + ((size_t)b * P_PIX + p0) * GK;

    float acc[4][4][4];
#pragma unroll
    for (int i = 0; i < 4; i++)
#pragma unroll
        for (int j = 0; j < 4; j++)
#pragma unroll
            for (int r = 0; r < 4; r++) acc[i][j][r] = 0.f;

    auto issue = [&](int chunk, int buf) {
        const int kb = chunk * BK;
        const uint32_t bufb = sm32 + (uint32_t)buf * 4 * AS * 2;
#pragma unroll
        for (int i = 0; i < 2; i++) {
            int idx = tid + i * 256;             // 0..511
            int row = idx >> 2, c8 = (idx & 3) * 8;
            size_t go = (size_t)row * GK + kb + c8;
            uint32_t so = bufb + (uint32_t)(row * A_STR + c8) * 2;
#pragma unroll
            for (int a = 0; a < 4; a++)
                cp_async16(so + (uint32_t)a * AS * 2, gA[a] + go);
        }
        CP_COMMIT();
    };

    issue(0, 0);
    issue(1, 1);

    for (int c = 0; c < NKC; c++) {
        if (c + 1 < NKC) CP_WAIT1(); else CP_WAIT0();
        __syncthreads();
        const uint32_t bufb = sm32 + (uint32_t)(c & 1) * 4 * AS * 2;
        const uint32_t sAh32 = bufb;
        const uint32_t sAl32 = bufb + AS * 2;
        const uint32_t sBh32 = bufb + 2 * AS * 2;
        const uint32_t sBl32 = bufb + 3 * AS * 2;

#pragma unroll
        for (int ks = 0; ks < BK / 16; ks++) {
            const int k0 = ks * 16;
            const int nrow = wc * 32 + (lane & 7);
            const int ncol = k0 + ((lane >> 3) & 1) * 8;
            const int arow = wr * 64 + (lane & 15);
            const int acol = k0 + (lane >> 4) * 8;

            uint32_t bH[4][2], aH[4][4];
#pragma unroll
            for (int nt = 0; nt < 4; nt++)
                ldsm_x2(bH[nt], sBh32 + (uint32_t)((nrow + nt * 8) * A_STR + ncol) * 2);
#pragma unroll
            for (int mt = 0; mt < 4; mt++)
                ldsm_x4(aH[mt], sAh32 + (uint32_t)((arow + mt * 16) * A_STR + acol) * 2);
            // pass 1: aH x bH  (16 independent chains)
#pragma unroll
            for (int mt = 0; mt < 4; mt++)
#pragma unroll
                for (int nt = 0; nt < 4; nt++)
                    mma_bf16(acc[mt][nt], aH[mt], bH[nt]);
            // pass 2: aH x bL
            uint32_t bL[4][2];
#pragma unroll
            for (int nt = 0; nt < 4; nt++)
                ldsm_x2(bL[nt], sBl32 + (uint32_t)((nrow + nt * 8) * A_STR + ncol) * 2);
#pragma unroll
            for (int mt = 0; mt < 4; mt++)
#pragma unroll
                for (int nt = 0; nt < 4; nt++)
                    mma_bf16(acc[mt][nt], aH[mt], bL[nt]);
            // pass 3: aL x bH
            uint32_t aL[4][4];
#pragma unroll
            for (int mt = 0; mt < 4; mt++)
                ldsm_x4(aL[mt], sAl32 + (uint32_t)((arow + mt * 16) * A_STR + acol) * 2);
#pragma unroll
            for (int mt = 0; mt < 4; mt++)
#pragma unroll
                for (int nt = 0; nt < 4; nt++)
                    mma_bf16(acc[mt][nt], aL[mt], bH[nt]);
        }
        __syncthreads();
        if (c + 2 < NKC) issue(c + 2, c & 1);
    }

    // epilogue
    const int tq = lane >> 2;
    const int tr4 = lane & 3;
#pragma unroll
    for (int mt = 0; mt < 4; mt++) {
#pragma unroll
        for (int nt = 0; nt < 4; nt++) {
            int m  = m0 + wr * 64 + mt * 16 + tq;
            int p  = p0 + wc * 32 + nt * 8 + tr4 * 2;
            float* y0 = &Y[((size_t)b * M + m) * P_PIX + p];
            *reinterpret_cast<float2*>(y0) = make_float2(acc[mt][nt][0], acc[mt][nt][1]);
            float* y1 = &Y[((size_t)b * M + m + 8) * P_PIX + p];
            *reinterpret_cast<float2*>(y1) = make_float2(acc[mt][nt][2], acc[mt][nt][3]);
        }
    }
}

// ---------------- depthwise 3x3, pad 1, 4 pixels/thread ----------------
__global__ __launch_bounds__(256) void dwconv_kernel(
    const float* __restrict__ in, const float* __restrict__ Wd, float* __restrict__ out)
{
    int gid = blockIdx.x * 256 + threadIdx.x;
    int grp = gid & 4095;
    int bc  = gid >> 12;
    int ch  = bc % NQKV;
    int x0 = (grp & 31) * 4, y = grp >> 5;
    const float* ip = in + (size_t)bc * P_PIX;
    const float* w  = Wd + ch * 9;
    float o0 = 0.f, o1 = 0.f, o2 = 0.f, o3 = 0.f;
#pragma unroll
    for (int dy = -1; dy <= 1; dy++) {
        int yy = y + dy;
        if ((unsigned)yy >= 128u) continue;
        const float* rp = ip + yy * 128;
        float v[6];
#pragma unroll
        for (int t = 0; t < 6; t++) {
            int xx = x0 - 1 + t;
            v[t] = ((unsigned)xx < 128u) ? rp[xx] : 0.f;
        }
#pragma unroll
        for (int dx = 0; dx < 3; dx++) {
            float wv = w[(dy + 1) * 3 + dx];
            o0 = fmaf(wv, v[dx + 0], o0);
            o1 = fmaf(wv, v[dx + 1], o1);
            o2 = fmaf(wv, v[dx + 2], o2);
            o3 = fmaf(wv, v[dx + 3], o3);
        }
    }
    *reinterpret_cast<float4*>(&out[(size_t)bc * P_PIX + y * 128 + x0]) =
        make_float4(o0, o1, o2, o3);
}

// ------ cattn raw dots + fused row sumsq, split-K partials ------------------
__global__ __launch_bounds__(256) void cattn_kernel(
    const float* __restrict__ dw, float* __restrict__ part, float* __restrict__ cnp)
{
    const int bh = blockIdx.y;
    const int b = bh >> 3, h = bh & 7;
    const int kbase = blockIdx.x * (P_PIX / CSPLIT);
    const float* qb = dw + ((size_t)b * NQKV + h * CH) * P_PIX;
    const float* kb = dw + ((size_t)b * NQKV + NCH + h * CH) * P_PIX;

    __shared__ float sq[CH][65];
    __shared__ float sk[CH][65];

    const int tid = threadIdx.x;
    const int ti = tid >> 4, tj = tid & 15;
    const int i0 = ti * 3, j0 = tj * 3;

    float acc[3][3];
#pragma unroll
    for (int r = 0; r < 3; r++)
#pragma unroll
        for (int c = 0; c < 3; c++) acc[r][c] = 0.f;
    float nrm = 0.f;

    for (int kc = 0; kc < P_PIX / CSPLIT; kc += 64) {
        const int kpos = kbase + kc;
        for (int e = tid; e < CH * 16; e += 256) {
            int r = e >> 4, c4 = (e & 15) * 4;
            float4 vq = *reinterpret_cast<const float4*>(&qb[(size_t)r * P_PIX + kpos + c4]);
            float4 vk = *reinterpret_cast<const float4*>(&kb[(size_t)r * P_PIX + kpos + c4]);
            sq[r][c4] = vq.x; sq[r][c4+1] = vq.y; sq[r][c4+2] = vq.z; sq[r][c4+3] = vq.w;
            sk[r][c4] = vk.x; sk[r][c4+1] = vk.y; sk[r][c4+2] = vk.z; sk[r][c4+3] = vk.w;
        }
        __syncthreads();
        // fused per-row sum of squares (threads 0..95: 48 q rows + 48 k rows)
        if (tid < 96) {
            const float* rowp = (tid < 48) ? &sq[tid][0] : &sk[tid - 48][0];
#pragma unroll 16
            for (int c = 0; c < 64; c++) nrm = fmaf(rowp[c], rowp[c], nrm);
        }
#pragma unroll 8
        for (int kk = 0; kk < 64; kk++) {
            float a0 = sq[i0][kk], a1 = sq[i0+1][kk], a2 = sq[i0+2][kk];
            float b0 = sk[j0][kk], b1 = sk[j0+1][kk], b2 = sk[j0+2][kk];
            acc[0][0] = fmaf(a0, b0, acc[0][0]);
            acc[0][1] = fmaf(a0, b1, acc[0][1]);
            acc[0][2] = fmaf(a0, b2, acc[0][2]);
            acc[1][0] = fmaf(a1, b0, acc[1][0]);
            acc[1][1] = fmaf(a1, b1, acc[1][1]);
            acc[1][2] = fmaf(a1, b2, acc[1][2]);
            acc[2][0] = fmaf(a2, b0, acc[2][0]);
            acc[2][1] = fmaf(a2, b1, acc[2][1]);
            acc[2][2] = fmaf(a2, b2, acc[2][2]);
        }
        __syncthreads();
    }
    float* pr = &part[((size_t)blockIdx.x * 16 + bh) * (CH * CH)];
#pragma unroll
    for (int r = 0; r < 3; r++)
#pragma unroll
        for (int c = 0; c < 3; c++)
            pr[(i0 + r) * CH + (j0 + c)] = acc[r][c];
    if (tid < 96)
        cnp[((size_t)blockIdx.x * 16 + bh) * 96 + tid] = nrm;
}

// ------- channel branch: combined top-k softmax coefficients ----------------
__global__ __launch_bounds__(256) void chan_coef_kernel(
    const float* __restrict__ part, const float* __restrict__ cnp,
    const float* __restrict__ temp,
    const float* __restrict__ w1p, const float* __restrict__ w2p,
    const float* __restrict__ w3p, const float* __restrict__ w4p,
    float* __restrict__ coef)
{
    const int warp = threadIdx.x >> 5, ln = threadIdx.x & 31;
    const int row = blockIdx.x * 8 + warp;
    const int bh = row / CH, i = row % CH;
    const int h = bh & 7;
    const float t = temp[h];
    const int KT[4] = {23, 31, 35, 37};
    float wts[4] = {w1p[0], w2p[0], w3p[0], w4p[0]};

    __shared__ float sa[8][CH];
    __shared__ float sth[8][4];

    int j0 = ln, j1 = ln + 32;
    // deterministic split-K reduction of dots and norms
    float d0 = 0.f, d1 = 0.f, sqi = 0.f, skk0 = 0.f, skk1 = 0.f;
    for (int s = 0; s < CSPLIT; s++) {
        const float* pr = part + ((size_t)s * 16 + bh) * (CH * CH) + i * CH;
        const float* np = cnp + ((size_t)s * 16 + bh) * 96;
        d0 += pr[j0];
        sqi += np[i];
        skk0 += np[48 + j0];
        if (j1 < CH) { d1 += pr[j1]; skk1 += np[48 + j1]; }
    }
    float inq = 1.f / fmaxf(sqrtf(sqi), 1e-12f);
    float nk0 = fmaxf(sqrtf(skk0), 1e-12f);
    float nk1 = fmaxf(sqrtf(skk1), 1e-12f);
    float a0 = d0 * inq / nk0 * t;
    float a1 = (j1 < CH) ? d1 * inq / nk1 * t : -INFINITY;
    sa[warp][j0] = a0;
    if (j1 < CH) sa[warp][j1] = a1;
    __syncwarp();

    int r0 = 0, r1 = 0;
    for (int q = 0; q < CH; q++) {
        float aq = sa[warp][q];
        r0 += (aq > a0) || (aq == a0 && q < j0);
        if (j1 < CH) r1 += (aq > a1) || (aq == a1 && q < j1);
    }
#pragma unroll
    for (int kx = 0; kx < 4; kx++) {
        if (r0 == KT[kx]) sth[warp][kx] = a0;
        if (j1 < CH && r1 == KT[kx]) sth[warp][kx] = a1;
    }
    __syncwarp();

    float m = fmaxf(a0, a1);
#pragma unroll
    for (int o = 16; o; o >>= 1) m = fmaxf(m, __shfl_xor_sync(0xffffffffu, m, o));
    float e0 = expf(a0 - m);
    float e1 = (j1 < CH) ? expf(a1 - m) : 0.f;

    float c0 = 0.f, c1 = 0.f;
#pragma unroll
    for (int kx = 0; kx < 4; kx++) {
        float th = sth[warp][kx];
        float zz = (a0 >= th ? e0 : 0.f) + ((j1 < CH && a1 >= th) ? e1 : 0.f);
#pragma unroll
        for (int o = 16; o; o >>= 1) zz += __shfl_xor_sync(0xffffffffu, zz, o);
        float f = wts[kx] / zz;
        if (a0 >= th) c0 += f;
        if (j1 < CH && a1 >= th) c1 += f;
    }
    coef[row * CH + j0] = e0 * c0;
    if (j1 < CH) coef[row * CH + j1] = e1 * c1;
}

// ------- cout = coef @ vc, packed i-pairs, broadcast shared loads -----------
__global__ __launch_bounds__(256) void cout_kernel(
    const float* __restrict__ coef, const float* __restrict__ dw,
    float* __restrict__ out)
{
    int bh = blockIdx.y; int b = bh >> 3, h = bh & 7;
    int p = blockIdx.x * 256 + threadIdx.x;
    __shared__ u64t scp[CH][CH / 2];
    const float* cf = coef + bh * CH * CH;
    for (int e = threadIdx.x; e < CH * (CH / 2); e += 256) {
        int j = e / (CH / 2), i2 = e % (CH / 2);
        scp[j][i2] = pack2(cf[(2 * i2) * CH + j], cf[(2 * i2 + 1) * CH + j]);
    }
    __syncthreads();
    const float* vb = dw + ((size_t)b * NQKV + 2 * NCH + h * CH) * P_PIX + p;
    u64t acc2[CH / 2];
#pragma unroll
    for (int i = 0; i < CH / 2; i++) acc2[i] = 0ull;
    for (int j = 0; j < CH; j++) {
        u64t vd = dup_f32(vb[(size_t)j * P_PIX]);
#pragma unroll
        for (int i = 0; i < CH / 2; i++) ffma2(acc2[i], vd, scp[j][i]);
    }
    float* ob = out + ((size_t)b * NCH + h * CH) * P_PIX + p;
#pragma unroll
    for (int i = 0; i < CH / 2; i++) {
        float lo, hi;
        asm("mov.b64 {%0, %1}, %2;" : "=f"(lo), "=f"(hi) : "l"(acc2[i]));
        ob[(size_t)(2 * i) * P_PIX]     = lo;
        ob[(size_t)(2 * i + 1) * P_PIX] = hi;
    }
}

// ------------- fused spatial window attention, register-tiled ----------------
#define SQ_STR 50
#define SAT_STR 66
__global__ __launch_bounds__(256) void spatial_kernel(
    const float* __restrict__ dw, const float* __restrict__ temp,
    const float* __restrict__ w1p, const float* __restrict__ w2p,
    const float* __restrict__ w3p, const float* __restrict__ w4p,
    float* __restrict__ out)
{
    extern __shared__ float smemf[];
    float* sq  = smemf;                      // 64*50 (later reused as obuf 48*66)
    float* sk2 = sq  + 64 * SQ_STR;          // 64*50
    float* svT = sk2 + 64 * SQ_STR;          // 48*66
    float* sat = svT + 48 * SAT_STR;         // 64*66
    float* nq  = sat + 64 * SAT_STR;         // 64
    float* nk  = nq  + 64;                   // 64
    float* sth = nk  + 64;                   // 64*4

    const int win = blockIdx.x;
    const int head = blockIdx.y;
    const int b = win >> 8, wy = (win >> 4) & 15, wx = win & 15;
    const int tid = threadIdx.x;
    const int ti = tid >> 4, tj = tid & 15;

    const size_t base = ((size_t)b * NQKV + head * CH) * P_PIX + (size_t)(wy * 8) * 128 + wx * 8;

    for (int e = tid; e < NWIN * CH; e += 256) {
        int c = e >> 6, n = e & 63;
        int iy = n >> 3, ix = n & 7;
        size_t off = (size_t)c * P_PIX + iy * 128 + ix;
        sq [n * SQ_STR + c] = dw[base + off];
        sk2[n * SQ_STR + c] = dw[base + (size_t)NCH * P_PIX + off];
        svT[c * SAT_STR + n] = dw[base + (size_t)(2 * NCH) * P_PIX + off];
    }
    __syncthreads();

    if (tid < 128) {
        int n = tid & 63;
        const float* src = (tid < 64) ? sq : sk2;
        float s = 0.f;
#pragma unroll
        for (int c = 0; c < CH; c++) { float v = src[n * SQ_STR + c]; s = fmaf(v, v, s); }
        float nn = fmaxf(sqrtf(s), 1e-12f);
        if (tid < 64) nq[n] = nn; else nk[n] = nn;
    }
    __syncthreads();

    const float t = temp[wx & 7];
    // QK^T: 4x4 tile per thread, interleaved: n = ti+16i, m = tj+16j
    {
        float accq[4][4];
#pragma unroll
        for (int i = 0; i < 4; i++)
#pragma unroll
            for (int j = 0; j < 4; j++) accq[i][j] = 0.f;
        for (int c = 0; c < CH; c++) {
            float qv[4], kv[4];
#pragma unroll
            for (int i = 0; i < 4; i++) qv[i] = sq[(ti + 16 * i) * SQ_STR + c];
#pragma unroll
            for (int j = 0; j < 4; j++) kv[j] = sk2[(tj + 16 * j) * SQ_STR + c];
#pragma unroll
            for (int i = 0; i < 4; i++)
#pragma unroll
                for (int j = 0; j < 4; j++)
                    accq[i][j] = fmaf(qv[i], kv[j], accq[i][j]);
        }
        float qn[4], kn[4];
#pragma unroll
        for (int i = 0; i < 4; i++) qn[i] = nq[ti + 16 * i];
#pragma unroll
        for (int j = 0; j < 4; j++) kn[j] = nk[tj + 16 * j];
#pragma unroll
        for (int i = 0; i < 4; i++)
#pragma unroll
            for (int j = 0; j < 4; j++)
                sat[(ti + 16 * i) * SAT_STR + tj + 16 * j] = accq[i][j] / (qn[i] * kn[j]) * t;
    }
    __syncthreads();

    const int warp = tid >> 5, ln = tid & 31;
    const int KT[4] = {31, 41, 47, 50};
    float wts[4] = {w1p[0], w2p[0], w3p[0], w4p[0]};

    for (int rr = 0; rr < 8; rr++) {
        int n = warp * 8 + rr;
        float a0 = sat[n * SAT_STR + ln];
        float a1 = sat[n * SAT_STR + ln + 32];
        int r0 = 0, r1 = 0;
        for (int i2 = 0; i2 < NWIN; i2++) {
            float ai = sat[n * SAT_STR + i2];
            r0 += (ai > a0) || (ai == a0 && i2 < ln);
            r1 += (ai > a1) || (ai == a1 && i2 < ln + 32);
        }
#pragma unroll
        for (int kx = 0; kx < 4; kx++) {
            if (r0 == KT[kx]) sth[n * 4 + kx] = a0;
            if (r1 == KT[kx]) sth[n * 4 + kx] = a1;
        }
        __syncwarp();

        float m = fmaxf(a0, a1);
#pragma unroll
        for (int o = 16; o; o >>= 1) m = fmaxf(m, __shfl_xor_sync(0xffffffffu, m, o));
        float e0 = expf(a0 - m), e1 = expf(a1 - m);

        float c0 = 0.f, c1 = 0.f;
#pragma unroll
        for (int kx = 0; kx < 4; kx++) {
            float th = sth[n * 4 + kx];
            float zz = (a0 >= th ? e0 : 0.f) + (a1 >= th ? e1 : 0.f);
#pragma unroll
            for (int o = 16; o; o >>= 1) zz += __shfl_xor_sync(0xffffffffu, zz, o);
            float f = wts[kx] / zz;
            if (a0 >= th) c0 += f;
            if (a1 >= th) c1 += f;
        }
        __syncwarp();
        sat[n * SAT_STR + ln]      = e0 * c0;
        sat[n * SAT_STR + ln + 32] = e1 * c1;
        __syncwarp();
    }
    __syncthreads();

    // A*V: 3x4 tile per thread: c = tj+16i, n = ti+16j; stage in obuf (= sq)
    {
        float acca[3][4];
#pragma unroll
        for (int i = 0; i < 3; i++)
#pragma unroll
            for (int j = 0; j < 4; j++) acca[i][j] = 0.f;
        for (int m = 0; m < NWIN; m++) {
            float av[4], vv[3];
#pragma unroll
            for (int j = 0; j < 4; j++) av[j] = sat[(ti + 16 * j) * SAT_STR + m];
#pragma unroll
            for (int i = 0; i < 3; i++) vv[i] = svT[(tj + 16 * i) * SAT_STR + m];
#pragma unroll
            for (int i = 0; i < 3; i++)
#pragma unroll
                for (int j = 0; j < 4; j++)
                    acca[i][j] = fmaf(av[j], vv[i], acca[i][j]);
        }
        float* obuf = sq;   // sq dead after QK^T
#pragma unroll
        for (int i = 0; i < 3; i++)
#pragma unroll
            for (int j = 0; j < 4; j++)
                obuf[(tj + 16 * i) * SAT_STR + ti + 16 * j] = acca[i][j];
    }
    __syncthreads();

    // coalesced global adds: p = wy*1024 + wx*64 + n
    {
        const float* obuf = sq;
#pragma unroll
        for (int o = 0; o < 12; o++) {
            int e = tid + o * 256;
            int c = e >> 6, n = e & 63;
            int p = wy * 1024 + wx * 64 + n;
            size_t oidx = ((size_t)b * NCH + head * CH + c) * P_PIX + p;
            out[oidx] += obuf[c * SAT_STR + n];
        }
    }
}

// ---------------- host launcher ----------------
extern "C" void kernel_launch(void* const* d_in, const int* in_sizes, int n_in,
                              void* d_out, int out_size)
{
    const float* x      = (const float*)d_in[0];
    const float* w_qkv  = (const float*)d_in[1];
    const float* w_dw   = (const float*)d_in[2];
    const float* w_proj = (const float*)d_in[3];
    const float* temp   = (const float*)d_in[4];
    const float* a1     = (const float*)d_in[5];
    const float* a2     = (const float*)d_in[6];
    const float* a3     = (const float*)d_in[7];
    const float* a4     = (const float*)d_in[8];
    float* out = (float*)d_out;

    float *qkv, *dwb, *sum, *cpart, *cnp, *ccoef;
    __nv_bfloat16 *xth, *xtl, *wqh, *wql, *wph, *wpl;
    cudaGetSymbolAddress((void**)&qkv,   g_qkv);
    cudaGetSymbolAddress((void**)&dwb,   g_dw);
    cudaGetSymbolAddress((void**)&sum,   g_sum);
    cudaGetSymbolAddress((void**)&cpart, g_cpart);
    cudaGetSymbolAddress((void**)&cnp,   g_cnp);
    cudaGetSymbolAddress((void**)&ccoef, g_ccoef);
    cudaGetSymbolAddress((void**)&xth,   g_xth);
    cudaGetSymbolAddress((void**)&xtl,   g_xtl);
    cudaGetSymbolAddress((void**)&wqh,   g_wqh);
    cudaGetSymbolAddress((void**)&wql,   g_wql);
    cudaGetSymbolAddress((void**)&wph,   g_wph);
    cudaGetSymbolAddress((void**)&wpl,   g_wpl);

    const int spatial_smem =
        (64 * SQ_STR * 2 + 48 * SAT_STR + 64 * SAT_STR + 64 + 64 + 64 * 4) * 4;
    const int gemm_smem = 2 * 4 * AS * 2;   // 81920 B
    cudaFuncSetAttribute(spatial_kernel, cudaFuncAttributeMaxDynamicSharedMemorySize, 65536);
    cudaFuncSetAttribute(hmma_gemm, cudaFuncAttributeMaxDynamicSharedMemorySize, gemm_smem);

    // 0) weight splits + X transpose/split
    convert_w<<<(NQKV * NCH + 255) / 256, 256>>>(w_qkv, wqh, wql, NQKV * NCH);
    convert_w<<<(NCH * NCH + 255) / 256, 256>>>(w_proj, wph, wpl, NCH * NCH);
    transpose_split<<<dim3(P_PIX / 32, GK / 32, 2), 256>>>(x, xth, xtl);
    // 1) qkv = 1x1 conv via split-bf16 HMMA (M=1152)
    hmma_gemm<<<dim3(P_PIX / 128, NQKV / 128, 2), 256, gemm_smem>>>(wqh, wql, xth, xtl, qkv, NQKV);
    // 2) depthwise 3x3
    dwconv_kernel<<<(2 * NQKV * P_PIX / 4) / 256, 256>>>(qkv, w_dw, dwb);
    // 3) cattn split-K partials + fused row norms
    cattn_kernel<<<dim3(CSPLIT, 16), 256>>>(dwb, cpart, cnp);
    // 4) channel softmax coefficients (reduces norms inline)
    chan_coef_kernel<<<96, 256>>>(cpart, cnp, temp, a1, a2, a3, a4, ccoef);
    // 5) cout = coef @ v
    cout_kernel<<<dim3(P_PIX / 256, 16), 256>>>(ccoef, dwb, sum);
    // 6) fused spatial window attention (adds into g_sum)
    spatial_kernel<<<dim3(512, HEADS), 256, spatial_smem>>>(dwb, temp, a1, a2, a3, a4, sum);
    // 7) proj: transpose/split g_sum, then HMMA GEMM (M=384) -> d_out
    transpose_split<<<dim3(P_PIX / 32, GK / 32, 2), 256>>>(sum, xth, xtl);
    hmma_gemm<<<dim3(P_PIX / 128, NCH / 128, 2), 256, gemm_smem>>>(wph, wpl, xth, xtl, out, NCH);
}